// round 5
// baseline (speedup 1.0000x reference)
#include <cuda_runtime.h>
#include <math.h>

// LSTM_38646115729591 — 2-layer bidirectional LSTM, fp32.
// T=512, B=64, D=512, H=512. Output [T,B,2H] fp32.

#define T_LEN 512
#define BATCH 64
#define HID   512
#define G4    2048
#define MROWS (T_LEN * BATCH)   // 32768
#define NBLK  128               // persistent grid (<=148 SMs -> co-resident)

#define W_STRIDE 516            // 512 + 4 pad (conflict-free rows)
#define SCRATCH_FLOATS 2048     // 256 threads x 8 partial sums
#define SMEM_FLOATS ((32 + 64) * W_STRIDE + SCRATCH_FLOATS)
#define SMEM_BYTES  (SMEM_FLOATS * 4)          // 206336 B (< 227KB opt-in)

typedef unsigned long long ull;

// ---- static device scratch (no runtime allocation allowed) ----
__device__ float g_xg_f[(size_t)MROWS * G4];       // 256 MB
__device__ float g_xg_b[(size_t)MROWS * G4];       // 256 MB
__device__ float g_l0[(size_t)MROWS * 2 * HID];    // 128 MB (layer0 output)
__device__ float g_h[2][2][BATCH * HID];           // [dir][ping][b*H]
__device__ unsigned g_cnt_leaf[8];                 // tree barrier leaves (16 ea)
__device__ unsigned g_cnt_root;                    // tree barrier root (8)
__device__ unsigned g_gen;

// ---- f32x2 helpers (FFMA2: 2x fp32 FMA rate on sm_103a) ----
__device__ __forceinline__ ull ffma2(ull a, ull b, ull c) {
    ull d;
    asm("fma.rn.f32x2 %0, %1, %2, %3;" : "=l"(d) : "l"(a), "l"(b), "l"(c));
    return d;
}
__device__ __forceinline__ float2 unpk(ull v) {
    float2 r;
    asm("mov.b64 {%0, %1}, %2;" : "=f"(r.x), "=f"(r.y) : "l"(v));
    return r;
}
__device__ __forceinline__ float sigf(float x) { return 1.0f / (1.0f + __expf(-x)); }

// =====================================================================
// SGEMM: C[M,N] = A[M,K] @ B[N,K]^T + b1[N] + b2[N]
// BM=BN=128, BK=8, 256 threads, 8x8 per-thread tile, FFMA2 accumulators.
// =====================================================================
__global__ __launch_bounds__(256) void sgemm_bias(
    const float* __restrict__ A, const float* __restrict__ B,
    const float* __restrict__ b1, const float* __restrict__ b2,
    float* __restrict__ C, int K, int N)
{
    __shared__ float As2[8][264];   // [k][2*m .. 2*m+1] duplicated pairs
    __shared__ float Bs[8][132];

    const int tid  = threadIdx.x;
    const int bm   = blockIdx.y * 128;
    const int bn   = blockIdx.x * 128;
    const int lrow = tid >> 1;
    const int lk   = (tid & 1) << 2;
    const int tx   = tid & 15;
    const int ty   = tid >> 4;

    const float* Ap = A + (size_t)(bm + lrow) * K + lk;
    const float* Bp = B + (size_t)(bn + lrow) * K + lk;

    ull acc[8][4];
#pragma unroll
    for (int i = 0; i < 8; i++)
#pragma unroll
        for (int j = 0; j < 4; j++) acc[i][j] = 0ULL;

    float4 av = *(const float4*)Ap;
    float4 bv = *(const float4*)Bp;

    for (int k0 = 0; k0 < K; k0 += 8) {
        *(float2*)&As2[lk + 0][lrow * 2] = make_float2(av.x, av.x);
        *(float2*)&As2[lk + 1][lrow * 2] = make_float2(av.y, av.y);
        *(float2*)&As2[lk + 2][lrow * 2] = make_float2(av.z, av.z);
        *(float2*)&As2[lk + 3][lrow * 2] = make_float2(av.w, av.w);
        Bs[lk + 0][lrow] = bv.x; Bs[lk + 1][lrow] = bv.y;
        Bs[lk + 2][lrow] = bv.z; Bs[lk + 3][lrow] = bv.w;
        __syncthreads();
        if (k0 + 8 < K) {
            av = *(const float4*)(Ap + k0 + 8);
            bv = *(const float4*)(Bp + k0 + 8);
        }
#pragma unroll
        for (int kk = 0; kk < 8; kk++) {
            const ulonglong2 a0 = *(const ulonglong2*)&As2[kk][ty * 8];
            const ulonglong2 a1 = *(const ulonglong2*)&As2[kk][ty * 8 + 4];
            const ulonglong2 a2 = *(const ulonglong2*)&As2[kk][128 + ty * 8];
            const ulonglong2 a3 = *(const ulonglong2*)&As2[kk][128 + ty * 8 + 4];
            const ulonglong2 p0 = *(const ulonglong2*)&Bs[kk][tx * 4];
            const ulonglong2 p1 = *(const ulonglong2*)&Bs[kk][64 + tx * 4];
            ull ad[8];
            ad[0] = a0.x; ad[1] = a0.y; ad[2] = a1.x; ad[3] = a1.y;
            ad[4] = a2.x; ad[5] = a2.y; ad[6] = a3.x; ad[7] = a3.y;
#pragma unroll
            for (int i = 0; i < 8; i++) {
                acc[i][0] = ffma2(ad[i], p0.x, acc[i][0]);
                acc[i][1] = ffma2(ad[i], p0.y, acc[i][1]);
                acc[i][2] = ffma2(ad[i], p1.x, acc[i][2]);
                acc[i][3] = ffma2(ad[i], p1.y, acc[i][3]);
            }
        }
        __syncthreads();
    }

#pragma unroll
    for (int i = 0; i < 8; i++) {
        const int m = bm + ((i < 4) ? (ty * 4 + i) : (64 + ty * 4 + (i - 4)));
#pragma unroll
        for (int j = 0; j < 4; j++) {
            const int n = bn + ((j < 2) ? (tx * 4 + 2 * j) : (64 + tx * 4 + 2 * (j - 2)));
            float2 v = unpk(acc[i][j]);
            v.x += b1[n] + b2[n];
            v.y += b1[n + 1] + b2[n + 1];
            *(float2*)&C[(size_t)m * N + n] = v;
        }
    }
}

// =====================================================================
// init_state
// =====================================================================
__global__ void init_state()
{
    const int i = blockIdx.x * blockDim.x + threadIdx.x;
    if (i < BATCH * HID) {
        g_h[0][0][i] = 0.0f; g_h[0][1][i] = 0.0f;
        g_h[1][0][i] = 0.0f; g_h[1][1][i] = 0.0f;
    }
    if (i < 8) g_cnt_leaf[i] = 0u;
    if (i == 0) { g_cnt_root = 0u; g_gen = 0u; }
}

// =====================================================================
// 2-level tree grid barrier: 8 leaves x 16 blocks, root of 8.
// Worst serialized-atomic chain = 16 + 8 (vs 128 flat).
// =====================================================================
__device__ __forceinline__ void grid_barrier(int bx)
{
    __syncthreads();
    if (threadIdx.x == 0) {
        __threadfence();                               // release block's writes
        const unsigned gen = *(volatile unsigned*)&g_gen;
        __threadfence();                               // order gen-read vs arrive
        const int g = bx >> 4;
        if (atomicAdd(&g_cnt_leaf[g], 1u) == 15u) {
            atomicExch(&g_cnt_leaf[g], 0u);            // safe: group all arrived
            if (atomicAdd(&g_cnt_root, 1u) == 7u) {
                atomicExch(&g_cnt_root, 0u);
                __threadfence();
                *(volatile unsigned*)&g_gen = gen + 1u;  // release all
            } else {
                while (*(volatile unsigned*)&g_gen == gen) { }
            }
        } else {
            while (*(volatile unsigned*)&g_gen == gen) { }
        }
        __threadfence();                               // acquire
    }
    __syncthreads();
}

// =====================================================================
// Persistent recurrence: all 512 steps of one layer, both directions.
// 128 blocks x 512 threads: dir = bx/64, hb = bx%64 (8 h-units).
// Thread (u = tid&7, bp = (tid>>3)&31, kh = tid>>8): 2 batches x 4 gates
// over k-half [kh*256, kh*256+256). Cross-kh reduction via smem scratch.
// W slice resident in smem; full h (64x512) staged per step.
// =====================================================================
__global__ __launch_bounds__(512) void lstm_persist(
    const float* __restrict__ xg_f, const float* __restrict__ xg_b,
    const float* __restrict__ whh_f, const float* __restrict__ whh_b,
    float* __restrict__ out)
{
    extern __shared__ float sm[];
    float (*wsm)[W_STRIDE] = (float(*)[W_STRIDE])sm;
    float (*hsm)[W_STRIDE] = (float(*)[W_STRIDE])(sm + 32 * W_STRIDE);
    float* psm = sm + 96 * W_STRIDE;                 // 2048-float scratch

    const int tid = threadIdx.x;
    const int bx  = blockIdx.x;
    const int dir = bx >> 6;
    const int hb  = bx & 63;
    const int u0  = hb * 8;
    const int u   = tid & 7;
    const int bp  = (tid >> 3) & 31;
    const int kh  = tid >> 8;                        // 0 or 1
    const int kb  = kh << 8;                         // k-base (floats)
    const int uu  = u0 + u;
    const int bb0 = 2 * bp, bb1 = 2 * bp + 1;

    const float* xg  = dir ? xg_b : xg_f;
    const float* whh = dir ? whh_b : whh_f;

    // ---- load W slice once: rows {g*512 + u0 + j}, j=0..7, g=0..3 ----
    for (int i = tid; i < 32 * 128; i += 512) {      // float4 index
        const int rr = i >> 7;
        const int c  = (i & 127) << 2;
        const int grow = (rr >> 3) * HID + u0 + (rr & 7);
        *(float4*)&wsm[rr][c] = *(const float4*)&whh[(size_t)grow * HID + c];
    }
    __syncthreads();

    float cp0 = 0.0f, cp1 = 0.0f;                    // cell state (kh==0 threads)

    for (int t = 0; t < T_LEN; t++) {
        const int t_eff = dir ? (T_LEN - 1 - t) : t;
        const int ping  = t & 1;
        const float* hprev = g_h[dir][ping];
        float*       hnext = g_h[dir][ping ^ 1];

        // prefetch xg rows for this step (kh==0 threads finalize)
        float xr[2][4];
        if (kh == 0) {
#pragma unroll
            for (int g = 0; g < 4; g++) {
                xr[0][g] = __ldg(&xg[((size_t)t_eff * BATCH + bb0) * G4 + g * HID + uu]);
                xr[1][g] = __ldg(&xg[((size_t)t_eff * BATCH + bb1) * G4 + g * HID + uu]);
            }
        }

        // ---- stage full h (64 x 512): 8192 float4, 16 per thread ----
#pragma unroll
        for (int rr = 0; rr < 2; rr++) {
            float4 v[8];
#pragma unroll
            for (int r = 0; r < 8; r++) {
                const int idx = tid + (rr * 8 + r) * 512;       // 0..8191
                v[r] = __ldcg((const float4*)&hprev[idx * 4]);
            }
#pragma unroll
            for (int r = 0; r < 8; r++) {
                const int idx = tid + (rr * 8 + r) * 512;
                *(float4*)&hsm[idx >> 7][(idx & 127) << 2] = v[r];
            }
        }
        __syncthreads();

        // ---- software-pipelined dot over this thread's k-half ----
        ull acc[2][4];
#pragma unroll
        for (int g = 0; g < 4; g++) { acc[0][g] = 0ULL; acc[1][g] = 0ULL; }

        ulonglong2 h0n = *(const ulonglong2*)&hsm[bb0][kb];
        ulonglong2 h1n = *(const ulonglong2*)&hsm[bb1][kb];
        ulonglong2 w0n = *(const ulonglong2*)&wsm[0 * 8 + u][kb];
        ulonglong2 w1n = *(const ulonglong2*)&wsm[1 * 8 + u][kb];
        ulonglong2 w2n = *(const ulonglong2*)&wsm[2 * 8 + u][kb];
        ulonglong2 w3n = *(const ulonglong2*)&wsm[3 * 8 + u][kb];

#pragma unroll 4
        for (int k4 = 0; k4 < 64; k4++) {
            const ulonglong2 h0 = h0n, h1 = h1n;
            const ulonglong2 w0 = w0n, w1 = w1n, w2 = w2n, w3 = w3n;
            const int kn = kb + (((k4 + 1) & 63) << 2);   // wrap: harmless reload
            h0n = *(const ulonglong2*)&hsm[bb0][kn];
            h1n = *(const ulonglong2*)&hsm[bb1][kn];
            w0n = *(const ulonglong2*)&wsm[0 * 8 + u][kn];
            w1n = *(const ulonglong2*)&wsm[1 * 8 + u][kn];
            w2n = *(const ulonglong2*)&wsm[2 * 8 + u][kn];
            w3n = *(const ulonglong2*)&wsm[3 * 8 + u][kn];
            acc[0][0] = ffma2(h0.x, w0.x, acc[0][0]);
            acc[1][0] = ffma2(h1.x, w0.x, acc[1][0]);
            acc[0][1] = ffma2(h0.x, w1.x, acc[0][1]);
            acc[1][1] = ffma2(h1.x, w1.x, acc[1][1]);
            acc[0][2] = ffma2(h0.x, w2.x, acc[0][2]);
            acc[1][2] = ffma2(h1.x, w2.x, acc[1][2]);
            acc[0][3] = ffma2(h0.x, w3.x, acc[0][3]);
            acc[1][3] = ffma2(h1.x, w3.x, acc[1][3]);
            acc[0][0] = ffma2(h0.y, w0.y, acc[0][0]);
            acc[1][0] = ffma2(h1.y, w0.y, acc[1][0]);
            acc[0][1] = ffma2(h0.y, w1.y, acc[0][1]);
            acc[1][1] = ffma2(h1.y, w1.y, acc[1][1]);
            acc[0][2] = ffma2(h0.y, w2.y, acc[0][2]);
            acc[1][2] = ffma2(h1.y, w2.y, acc[1][2]);
            acc[0][3] = ffma2(h0.y, w3.y, acc[0][3]);
            acc[1][3] = ffma2(h1.y, w3.y, acc[1][3]);
        }

        // ---- cross-kh reduction: kh==1 stores partials, kh==0 finishes ----
        float s[2][4];
#pragma unroll
        for (int bi = 0; bi < 2; bi++)
#pragma unroll
            for (int g = 0; g < 4; g++) {
                const float2 v = unpk(acc[bi][g]);
                s[bi][g] = v.x + v.y;
            }

        if (kh == 1) {
            float* p = &psm[(bp * 8 + u) * 8];
#pragma unroll
            for (int bi = 0; bi < 2; bi++)
#pragma unroll
                for (int g = 0; g < 4; g++) p[bi * 4 + g] = s[bi][g];
        }
        __syncthreads();

        if (kh == 0) {
            const float* p = &psm[(bp * 8 + u) * 8];
            {
                const float gi = s[0][0] + p[0] + xr[0][0];
                const float gf = s[0][1] + p[1] + xr[0][1];
                const float gg = s[0][2] + p[2] + xr[0][2];
                const float go = s[0][3] + p[3] + xr[0][3];
                cp0 = sigf(gf) * cp0 + sigf(gi) * tanhf(gg);
                const float hn = sigf(go) * tanhf(cp0);
                __stcg(&hnext[bb0 * HID + uu], hn);
                out[((size_t)t_eff * BATCH + bb0) * (2 * HID) + dir * HID + uu] = hn;
            }
            {
                const float gi = s[1][0] + p[4] + xr[1][0];
                const float gf = s[1][1] + p[5] + xr[1][1];
                const float gg = s[1][2] + p[6] + xr[1][2];
                const float go = s[1][3] + p[7] + xr[1][3];
                cp1 = sigf(gf) * cp1 + sigf(gi) * tanhf(gg);
                const float hn = sigf(go) * tanhf(cp1);
                __stcg(&hnext[bb1 * HID + uu], hn);
                out[((size_t)t_eff * BATCH + bb1) * (2 * HID) + dir * HID + uu] = hn;
            }
        }

        grid_barrier(bx);
    }
}

// =====================================================================
// host
// =====================================================================
extern "C" void kernel_launch(void* const* d_in, const int* in_sizes, int n_in,
                              void* d_out, int out_size)
{
    const float* x       = (const float*)d_in[0];
    const float* w_ih0_f = (const float*)d_in[1];
    const float* w_hh0_f = (const float*)d_in[2];
    const float* b_ih0_f = (const float*)d_in[3];
    const float* b_hh0_f = (const float*)d_in[4];
    const float* w_ih0_b = (const float*)d_in[5];
    const float* w_hh0_b = (const float*)d_in[6];
    const float* b_ih0_b = (const float*)d_in[7];
    const float* b_hh0_b = (const float*)d_in[8];
    const float* w_ih1_f = (const float*)d_in[9];
    const float* w_hh1_f = (const float*)d_in[10];
    const float* b_ih1_f = (const float*)d_in[11];
    const float* b_hh1_f = (const float*)d_in[12];
    const float* w_ih1_b = (const float*)d_in[13];
    const float* w_hh1_b = (const float*)d_in[14];
    const float* b_ih1_b = (const float*)d_in[15];
    const float* b_hh1_b = (const float*)d_in[16];
    float* out = (float*)d_out;

    float *xg_f, *xg_b, *l0;
    cudaGetSymbolAddress((void**)&xg_f, g_xg_f);
    cudaGetSymbolAddress((void**)&xg_b, g_xg_b);
    cudaGetSymbolAddress((void**)&l0,   g_l0);

    cudaFuncSetAttribute(lstm_persist,
                         cudaFuncAttributeMaxDynamicSharedMemorySize, SMEM_BYTES);

    const dim3 gemm_grid(G4 / 128, MROWS / 128);   // (16, 256)

    // ---- layer 0 ----
    sgemm_bias<<<gemm_grid, 256>>>(x, w_ih0_f, b_ih0_f, b_hh0_f, xg_f, 512, G4);
    sgemm_bias<<<gemm_grid, 256>>>(x, w_ih0_b, b_ih0_b, b_hh0_b, xg_b, 512, G4);
    init_state<<<128, 256>>>();
    lstm_persist<<<NBLK, 512, SMEM_BYTES>>>(xg_f, xg_b, w_hh0_f, w_hh0_b, l0);

    // ---- layer 1 (K = 1024) ----
    sgemm_bias<<<gemm_grid, 256>>>(l0, w_ih1_f, b_ih1_f, b_hh1_f, xg_f, 1024, G4);
    sgemm_bias<<<gemm_grid, 256>>>(l0, w_ih1_b, b_ih1_b, b_hh1_b, xg_b, 1024, G4);
    init_state<<<128, 256>>>();
    lstm_persist<<<NBLK, 512, SMEM_BYTES>>>(xg_f, xg_b, w_hh1_f, w_hh1_b, out);
}

// round 6
// speedup vs baseline: 1.1797x; 1.1797x over previous
#include <cuda_runtime.h>
#include <math.h>

// LSTM_38646115729591 — 2-layer bidirectional LSTM, fp32.
// T=512, B=64, D=512, H=512. Output [T,B,2H] fp32.

#define T_LEN 512
#define BATCH 64
#define HID   512
#define G4    2048
#define MROWS (T_LEN * BATCH)   // 32768
#define NBLK  128               // persistent grid (<=148 SMs -> co-resident)

#define W_STRIDE 516            // 512 + 4 pad, 16B-aligned rows
#define PSM_STRIDE 20
#define PSM_FLOATS (128 * PSM_STRIDE)              // 2560
#define SMEM_FLOATS ((32 + 64) * W_STRIDE + PSM_FLOATS)
#define SMEM_BYTES  (SMEM_FLOATS * 4)              // 208384 B

typedef unsigned long long ull;

// ---- static device scratch (no runtime allocation allowed) ----
__device__ float g_xg_f[(size_t)MROWS * G4];       // 256 MB
__device__ float g_xg_b[(size_t)MROWS * G4];       // 256 MB
__device__ float g_l0[(size_t)MROWS * 2 * HID];    // 128 MB (layer0 output)
__device__ float g_h[2][2][BATCH * HID];           // [dir][ping][b*H]
__device__ unsigned g_cnt_leaf[2][4];              // per-dir tree leaves (16 ea)
__device__ unsigned g_cnt_root[2];                 // per-dir root (4)
__device__ unsigned g_gen[2];

// ---- f32x2 helpers (FFMA2: 2x fp32 FMA rate on sm_103a) ----
__device__ __forceinline__ ull ffma2(ull a, ull b, ull c) {
    ull d;
    asm("fma.rn.f32x2 %0, %1, %2, %3;" : "=l"(d) : "l"(a), "l"(b), "l"(c));
    return d;
}
__device__ __forceinline__ float2 unpk(ull v) {
    float2 r;
    asm("mov.b64 {%0, %1}, %2;" : "=f"(r.x), "=f"(r.y) : "l"(v));
    return r;
}
__device__ __forceinline__ float sigf(float x) { return 1.0f / (1.0f + __expf(-x)); }

// ---- scoped sync primitives (no MEMBAR.GPU / CCTL.IVALL) ----
__device__ __forceinline__ unsigned atom_add_acqrel(unsigned* p, unsigned v) {
    unsigned old;
    asm volatile("atom.add.acq_rel.gpu.u32 %0, [%1], %2;"
                 : "=r"(old) : "l"(p), "r"(v) : "memory");
    return old;
}
__device__ __forceinline__ unsigned ld_acq(const unsigned* p) {
    unsigned v;
    asm volatile("ld.acquire.gpu.u32 %0, [%1];" : "=r"(v) : "l"(p) : "memory");
    return v;
}
__device__ __forceinline__ void st_rel(unsigned* p, unsigned v) {
    asm volatile("st.release.gpu.u32 [%0], %1;" :: "l"(p), "r"(v) : "memory");
}
__device__ __forceinline__ void st_rlx(unsigned* p, unsigned v) {
    asm volatile("st.relaxed.gpu.u32 [%0], %1;" :: "l"(p), "r"(v) : "memory");
}

// =====================================================================
// SGEMM: C[M,N] = A[M,K] @ B[N,K]^T + b1[N] + b2[N]   (unchanged)
// =====================================================================
__global__ __launch_bounds__(256) void sgemm_bias(
    const float* __restrict__ A, const float* __restrict__ B,
    const float* __restrict__ b1, const float* __restrict__ b2,
    float* __restrict__ C, int K, int N)
{
    __shared__ float As2[8][264];
    __shared__ float Bs[8][132];

    const int tid  = threadIdx.x;
    const int bm   = blockIdx.y * 128;
    const int bn   = blockIdx.x * 128;
    const int lrow = tid >> 1;
    const int lk   = (tid & 1) << 2;
    const int tx   = tid & 15;
    const int ty   = tid >> 4;

    const float* Ap = A + (size_t)(bm + lrow) * K + lk;
    const float* Bp = B + (size_t)(bn + lrow) * K + lk;

    ull acc[8][4];
#pragma unroll
    for (int i = 0; i < 8; i++)
#pragma unroll
        for (int j = 0; j < 4; j++) acc[i][j] = 0ULL;

    float4 av = *(const float4*)Ap;
    float4 bv = *(const float4*)Bp;

    for (int k0 = 0; k0 < K; k0 += 8) {
        *(float2*)&As2[lk + 0][lrow * 2] = make_float2(av.x, av.x);
        *(float2*)&As2[lk + 1][lrow * 2] = make_float2(av.y, av.y);
        *(float2*)&As2[lk + 2][lrow * 2] = make_float2(av.z, av.z);
        *(float2*)&As2[lk + 3][lrow * 2] = make_float2(av.w, av.w);
        Bs[lk + 0][lrow] = bv.x; Bs[lk + 1][lrow] = bv.y;
        Bs[lk + 2][lrow] = bv.z; Bs[lk + 3][lrow] = bv.w;
        __syncthreads();
        if (k0 + 8 < K) {
            av = *(const float4*)(Ap + k0 + 8);
            bv = *(const float4*)(Bp + k0 + 8);
        }
#pragma unroll
        for (int kk = 0; kk < 8; kk++) {
            const ulonglong2 a0 = *(const ulonglong2*)&As2[kk][ty * 8];
            const ulonglong2 a1 = *(const ulonglong2*)&As2[kk][ty * 8 + 4];
            const ulonglong2 a2 = *(const ulonglong2*)&As2[kk][128 + ty * 8];
            const ulonglong2 a3 = *(const ulonglong2*)&As2[kk][128 + ty * 8 + 4];
            const ulonglong2 p0 = *(const ulonglong2*)&Bs[kk][tx * 4];
            const ulonglong2 p1 = *(const ulonglong2*)&Bs[kk][64 + tx * 4];
            ull ad[8];
            ad[0] = a0.x; ad[1] = a0.y; ad[2] = a1.x; ad[3] = a1.y;
            ad[4] = a2.x; ad[5] = a2.y; ad[6] = a3.x; ad[7] = a3.y;
#pragma unroll
            for (int i = 0; i < 8; i++) {
                acc[i][0] = ffma2(ad[i], p0.x, acc[i][0]);
                acc[i][1] = ffma2(ad[i], p0.y, acc[i][1]);
                acc[i][2] = ffma2(ad[i], p1.x, acc[i][2]);
                acc[i][3] = ffma2(ad[i], p1.y, acc[i][3]);
            }
        }
        __syncthreads();
    }

#pragma unroll
    for (int i = 0; i < 8; i++) {
        const int m = bm + ((i < 4) ? (ty * 4 + i) : (64 + ty * 4 + (i - 4)));
#pragma unroll
        for (int j = 0; j < 4; j++) {
            const int n = bn + ((j < 2) ? (tx * 4 + 2 * j) : (64 + tx * 4 + 2 * (j - 2)));
            float2 v = unpk(acc[i][j]);
            v.x += b1[n] + b2[n];
            v.y += b1[n + 1] + b2[n + 1];
            *(float2*)&C[(size_t)m * N + n] = v;
        }
    }
}

// =====================================================================
// init_state
// =====================================================================
__global__ void init_state()
{
    const int i = blockIdx.x * blockDim.x + threadIdx.x;
    if (i < BATCH * HID) {
        g_h[0][0][i] = 0.0f; g_h[0][1][i] = 0.0f;
        g_h[1][0][i] = 0.0f; g_h[1][1][i] = 0.0f;
    }
    if (i < 4) { g_cnt_leaf[0][i] = 0u; g_cnt_leaf[1][i] = 0u; }
    if (i < 2) { g_cnt_root[i] = 0u; g_gen[i] = 0u; }
}

// =====================================================================
// Per-direction tree barrier: 4 leaves x 16 blocks, root of 4.
// Scoped acq/rel atomics only — no full GPU membar, no L1D flush.
// =====================================================================
__device__ __forceinline__ void dir_barrier(int dir, int bx)
{
    __syncthreads();
    if (threadIdx.x == 0) {
        unsigned* gen_p = &g_gen[dir];
        const unsigned gen = ld_acq(gen_p);
        const int g = (bx & 63) >> 4;
        if (atom_add_acqrel(&g_cnt_leaf[dir][g], 1u) == 15u) {
            st_rlx(&g_cnt_leaf[dir][g], 0u);        // safe: group fully arrived
            if (atom_add_acqrel(&g_cnt_root[dir], 1u) == 3u) {
                st_rlx(&g_cnt_root[dir], 0u);
                st_rel(gen_p, gen + 1u);            // release all
            } else {
                while (ld_acq(gen_p) == gen) { }
            }
        } else {
            while (ld_acq(gen_p) == gen) { }
        }
    }
    __syncthreads();
}

// =====================================================================
// Persistent recurrence: 512 steps of one layer, both directions.
// 128 blocks x 256 threads: dir = bx/64, hb = bx%64 (8 h-units).
// Thread (u = tid&7, bq = (tid>>3)&15, kh = tid>>7):
//   4 batches {bq, bq+16, bq+32, bq+48} x 4 gates over k-half kh.
//   Per k4: 8 LDS.128 -> 32 FFMA2 (2 B/FMA). Conflict-free (dRow=1).
// W slice resident in smem; full h (64x512) staged per step.
// =====================================================================
__global__ __launch_bounds__(256) void lstm_persist(
    const float* __restrict__ xg_f, const float* __restrict__ xg_b,
    const float* __restrict__ whh_f, const float* __restrict__ whh_b,
    float* __restrict__ out)
{
    extern __shared__ float sm[];
    float (*wsm)[W_STRIDE] = (float(*)[W_STRIDE])sm;
    float (*hsm)[W_STRIDE] = (float(*)[W_STRIDE])(sm + 32 * W_STRIDE);
    float* psm = sm + 96 * W_STRIDE;                 // 2560-float scratch

    const int tid = threadIdx.x;
    const int bx  = blockIdx.x;
    const int dir = bx >> 6;
    const int hb  = bx & 63;
    const int u0  = hb * 8;
    const int u   = tid & 7;
    const int bq  = (tid >> 3) & 15;
    const int kh  = tid >> 7;                        // 0 or 1
    const int kb  = kh << 8;                         // k-base (floats)
    const int uu  = u0 + u;
    const int pidx = (bq * 8 + u) * PSM_STRIDE;

    const float* xg  = dir ? xg_b : xg_f;
    const float* whh = dir ? whh_b : whh_f;

    // ---- load W slice once: rows {g*512 + u0 + j}, j=0..7, g=0..3 ----
    for (int i = tid; i < 32 * 128; i += 256) {      // float4 index
        const int rr = i >> 7;
        const int c  = (i & 127) << 2;
        const int grow = (rr >> 3) * HID + u0 + (rr & 7);
        *(float4*)&wsm[rr][c] = *(const float4*)&whh[(size_t)grow * HID + c];
    }
    __syncthreads();

    float cp[4] = {0.0f, 0.0f, 0.0f, 0.0f};         // cell state (kh==0)

    for (int t = 0; t < T_LEN; t++) {
        const int t_eff = dir ? (T_LEN - 1 - t) : t;
        const int ping  = t & 1;
        const float* hprev = g_h[dir][ping];
        float*       hnext = g_h[dir][ping ^ 1];

        // prefetch xg rows for this step (kh==0 threads finalize)
        float xr[4][4];
        if (kh == 0) {
#pragma unroll
            for (int j = 0; j < 4; j++) {
                const int b = bq + j * 16;
#pragma unroll
                for (int g = 0; g < 4; g++)
                    xr[j][g] = __ldg(&xg[((size_t)t_eff * BATCH + b) * G4 + g * HID + uu]);
            }
        }

        // ---- stage full h (64 x 512): 8192 float4, 32 per thread ----
#pragma unroll
        for (int rr = 0; rr < 4; rr++) {
            float4 v[8];
#pragma unroll
            for (int r = 0; r < 8; r++) {
                const int idx = tid + (rr * 8 + r) * 256;       // 0..8191
                v[r] = __ldcg((const float4*)&hprev[idx * 4]);
            }
#pragma unroll
            for (int r = 0; r < 8; r++) {
                const int idx = tid + (rr * 8 + r) * 256;
                *(float4*)&hsm[idx >> 7][(idx & 127) << 2] = v[r];
            }
        }
        __syncthreads();

        // ---- software-pipelined 4b x 4g dot over this k-half ----
        ull acc[4][4];
#pragma unroll
        for (int j = 0; j < 4; j++)
#pragma unroll
            for (int g = 0; g < 4; g++) acc[j][g] = 0ULL;

        ulonglong2 hn[4], wn[4];
#pragma unroll
        for (int j = 0; j < 4; j++)
            hn[j] = *(const ulonglong2*)&hsm[bq + j * 16][kb];
#pragma unroll
        for (int g = 0; g < 4; g++)
            wn[g] = *(const ulonglong2*)&wsm[g * 8 + u][kb];

#pragma unroll 2
        for (int k4 = 0; k4 < 64; k4++) {
            const ulonglong2 h0 = hn[0], h1 = hn[1], h2 = hn[2], h3 = hn[3];
            const ulonglong2 w0 = wn[0], w1 = wn[1], w2 = wn[2], w3 = wn[3];
            const int kn = kb + (k4 + 1) * 4;        // last iter reads row pad
            hn[0] = *(const ulonglong2*)&hsm[bq +  0][kn];
            hn[1] = *(const ulonglong2*)&hsm[bq + 16][kn];
            hn[2] = *(const ulonglong2*)&hsm[bq + 32][kn];
            hn[3] = *(const ulonglong2*)&hsm[bq + 48][kn];
            wn[0] = *(const ulonglong2*)&wsm[0 * 8 + u][kn];
            wn[1] = *(const ulonglong2*)&wsm[1 * 8 + u][kn];
            wn[2] = *(const ulonglong2*)&wsm[2 * 8 + u][kn];
            wn[3] = *(const ulonglong2*)&wsm[3 * 8 + u][kn];
            acc[0][0] = ffma2(h0.x, w0.x, acc[0][0]);
            acc[1][0] = ffma2(h1.x, w0.x, acc[1][0]);
            acc[2][0] = ffma2(h2.x, w0.x, acc[2][0]);
            acc[3][0] = ffma2(h3.x, w0.x, acc[3][0]);
            acc[0][1] = ffma2(h0.x, w1.x, acc[0][1]);
            acc[1][1] = ffma2(h1.x, w1.x, acc[1][1]);
            acc[2][1] = ffma2(h2.x, w1.x, acc[2][1]);
            acc[3][1] = ffma2(h3.x, w1.x, acc[3][1]);
            acc[0][2] = ffma2(h0.x, w2.x, acc[0][2]);
            acc[1][2] = ffma2(h1.x, w2.x, acc[1][2]);
            acc[2][2] = ffma2(h2.x, w2.x, acc[2][2]);
            acc[3][2] = ffma2(h3.x, w2.x, acc[3][2]);
            acc[0][3] = ffma2(h0.x, w3.x, acc[0][3]);
            acc[1][3] = ffma2(h1.x, w3.x, acc[1][3]);
            acc[2][3] = ffma2(h2.x, w3.x, acc[2][3]);
            acc[3][3] = ffma2(h3.x, w3.x, acc[3][3]);
            acc[0][0] = ffma2(h0.y, w0.y, acc[0][0]);
            acc[1][0] = ffma2(h1.y, w0.y, acc[1][0]);
            acc[2][0] = ffma2(h2.y, w0.y, acc[2][0]);
            acc[3][0] = ffma2(h3.y, w0.y, acc[3][0]);
            acc[0][1] = ffma2(h0.y, w1.y, acc[0][1]);
            acc[1][1] = ffma2(h1.y, w1.y, acc[1][1]);
            acc[2][1] = ffma2(h2.y, w1.y, acc[2][1]);
            acc[3][1] = ffma2(h3.y, w1.y, acc[3][1]);
            acc[0][2] = ffma2(h0.y, w2.y, acc[0][2]);
            acc[1][2] = ffma2(h1.y, w2.y, acc[1][2]);
            acc[2][2] = ffma2(h2.y, w2.y, acc[2][2]);
            acc[3][2] = ffma2(h3.y, w2.y, acc[3][2]);
            acc[0][3] = ffma2(h0.y, w3.y, acc[0][3]);
            acc[1][3] = ffma2(h1.y, w3.y, acc[1][3]);
            acc[2][3] = ffma2(h2.y, w3.y, acc[2][3]);
            acc[3][3] = ffma2(h3.y, w3.y, acc[3][3]);
        }

        // ---- collapse f32x2 pairs ----
        float s[4][4];
#pragma unroll
        for (int j = 0; j < 4; j++)
#pragma unroll
            for (int g = 0; g < 4; g++) {
                const float2 v = unpk(acc[j][g]);
                s[j][g] = v.x + v.y;
            }

        // ---- cross-kh reduction ----
        if (kh == 1) {
#pragma unroll
            for (int j = 0; j < 4; j++)
                *(float4*)&psm[pidx + j * 4] =
                    make_float4(s[j][0], s[j][1], s[j][2], s[j][3]);
        }
        __syncthreads();

        if (kh == 0) {
#pragma unroll
            for (int j = 0; j < 4; j++) {
                const int b = bq + j * 16;
                const float4 p = *(const float4*)&psm[pidx + j * 4];
                const float gi = s[j][0] + p.x + xr[j][0];
                const float gf = s[j][1] + p.y + xr[j][1];
                const float gg = s[j][2] + p.z + xr[j][2];
                const float go = s[j][3] + p.w + xr[j][3];
                cp[j] = sigf(gf) * cp[j] + sigf(gi) * tanhf(gg);
                const float hv = sigf(go) * tanhf(cp[j]);
                __stcg(&hnext[b * HID + uu], hv);
                out[((size_t)t_eff * BATCH + b) * (2 * HID) + dir * HID + uu] = hv;
            }
        }

        dir_barrier(dir, bx);
    }
}

// =====================================================================
// host
// =====================================================================
extern "C" void kernel_launch(void* const* d_in, const int* in_sizes, int n_in,
                              void* d_out, int out_size)
{
    const float* x       = (const float*)d_in[0];
    const float* w_ih0_f = (const float*)d_in[1];
    const float* w_hh0_f = (const float*)d_in[2];
    const float* b_ih0_f = (const float*)d_in[3];
    const float* b_hh0_f = (const float*)d_in[4];
    const float* w_ih0_b = (const float*)d_in[5];
    const float* w_hh0_b = (const float*)d_in[6];
    const float* b_ih0_b = (const float*)d_in[7];
    const float* b_hh0_b = (const float*)d_in[8];
    const float* w_ih1_f = (const float*)d_in[9];
    const float* w_hh1_f = (const float*)d_in[10];
    const float* b_ih1_f = (const float*)d_in[11];
    const float* b_hh1_f = (const float*)d_in[12];
    const float* w_ih1_b = (const float*)d_in[13];
    const float* w_hh1_b = (const float*)d_in[14];
    const float* b_ih1_b = (const float*)d_in[15];
    const float* b_hh1_b = (const float*)d_in[16];
    float* out = (float*)d_out;

    float *xg_f, *xg_b, *l0;
    cudaGetSymbolAddress((void**)&xg_f, g_xg_f);
    cudaGetSymbolAddress((void**)&xg_b, g_xg_b);
    cudaGetSymbolAddress((void**)&l0,   g_l0);

    cudaFuncSetAttribute(lstm_persist,
                         cudaFuncAttributeMaxDynamicSharedMemorySize, SMEM_BYTES);

    const dim3 gemm_grid(G4 / 128, MROWS / 128);   // (16, 256)

    // ---- layer 0 ----
    sgemm_bias<<<gemm_grid, 256>>>(x, w_ih0_f, b_ih0_f, b_hh0_f, xg_f, 512, G4);
    sgemm_bias<<<gemm_grid, 256>>>(x, w_ih0_b, b_ih0_b, b_hh0_b, xg_b, 512, G4);
    init_state<<<128, 256>>>();
    lstm_persist<<<NBLK, 256, SMEM_BYTES>>>(xg_f, xg_b, w_hh0_f, w_hh0_b, l0);

    // ---- layer 1 (K = 1024) ----
    sgemm_bias<<<gemm_grid, 256>>>(l0, w_ih1_f, b_ih1_f, b_hh1_f, xg_f, 1024, G4);
    sgemm_bias<<<gemm_grid, 256>>>(l0, w_ih1_b, b_ih1_b, b_hh1_b, xg_b, 1024, G4);
    init_state<<<128, 256>>>();
    lstm_persist<<<NBLK, 256, SMEM_BYTES>>>(xg_f, xg_b, w_hh1_f, w_hh1_b, out);
}

// round 9
// speedup vs baseline: 1.5554x; 1.3184x over previous
#include <cuda_runtime.h>
#include <cuda_bf16.h>
#include <cstdint>
#include <math.h>

// LSTM_38646115729591 — 2-layer bidirectional LSTM.
// T=512, B=64, D=512, H=512. Output [T,B,2H] fp32.
// Input GEMMs: mma.sync bf16 (compute_103-safe) with 2-term hi/lo split.
// Recurrence: persistent fp32 FFMA2 kernel (round-6 passing version).

#define T_LEN 512
#define BATCH 64
#define HID   512
#define G4    2048
#define MROWS (T_LEN * BATCH)   // 32768
#define NBLK  128

#define W_STRIDE 516
#define PSM_STRIDE 20
#define PSM_FLOATS (128 * PSM_STRIDE)
#define SMEM_FLOATS ((32 + 64) * W_STRIDE + PSM_FLOATS)
#define SMEM_BYTES  (SMEM_FLOATS * 4)              // 208384 B

typedef unsigned long long ull;

// ---- static device scratch ----
__device__ float g_xg_f[(size_t)MROWS * G4];
__device__ float g_xg_b[(size_t)MROWS * G4];
__device__ float g_l0[(size_t)MROWS * 2 * HID];
__device__ float g_h[2][2][BATCH * HID];
__device__ unsigned g_cnt_leaf[2][4];
__device__ unsigned g_cnt_root[2];
__device__ unsigned g_gen[2];

__device__ __nv_bfloat16 g_a_hi[(size_t)MROWS * 1024];
__device__ __nv_bfloat16 g_a_lo[(size_t)MROWS * 1024];
__device__ __nv_bfloat16 g_whi_f[(size_t)G4 * 1024];
__device__ __nv_bfloat16 g_wlo_f[(size_t)G4 * 1024];
__device__ __nv_bfloat16 g_whi_b[(size_t)G4 * 1024];
__device__ __nv_bfloat16 g_wlo_b[(size_t)G4 * 1024];

// ---- f32x2 helpers ----
__device__ __forceinline__ ull ffma2(ull a, ull b, ull c) {
    ull d;
    asm("fma.rn.f32x2 %0, %1, %2, %3;" : "=l"(d) : "l"(a), "l"(b), "l"(c));
    return d;
}
__device__ __forceinline__ float2 unpk(ull v) {
    float2 r;
    asm("mov.b64 {%0, %1}, %2;" : "=f"(r.x), "=f"(r.y) : "l"(v));
    return r;
}
__device__ __forceinline__ float sigf(float x) { return 1.0f / (1.0f + __expf(-x)); }

// ---- scoped sync primitives ----
__device__ __forceinline__ unsigned atom_add_acqrel(unsigned* p, unsigned v) {
    unsigned old;
    asm volatile("atom.add.acq_rel.gpu.u32 %0, [%1], %2;"
                 : "=r"(old) : "l"(p), "r"(v) : "memory");
    return old;
}
__device__ __forceinline__ unsigned ld_acq(const unsigned* p) {
    unsigned v;
    asm volatile("ld.acquire.gpu.u32 %0, [%1];" : "=r"(v) : "l"(p) : "memory");
    return v;
}
__device__ __forceinline__ void st_rel(unsigned* p, unsigned v) {
    asm volatile("st.release.gpu.u32 [%0], %1;" :: "l"(p), "r"(v) : "memory");
}
__device__ __forceinline__ void st_rlx(unsigned* p, unsigned v) {
    asm volatile("st.relaxed.gpu.u32 [%0], %1;" :: "l"(p), "r"(v) : "memory");
}

// ---- mma.sync helpers (sm_80 baseline PTX — valid on compute_103) ----
__device__ __forceinline__ uint32_t s2u(const void* p) {
    return (uint32_t)__cvta_generic_to_shared(p);
}
__device__ __forceinline__ void ldsm4(uint32_t* r, uint32_t addr) {
    asm volatile(
        "ldmatrix.sync.aligned.m8n8.x4.shared.b16 {%0,%1,%2,%3}, [%4];"
        : "=r"(r[0]), "=r"(r[1]), "=r"(r[2]), "=r"(r[3]) : "r"(addr));
}
__device__ __forceinline__ void mma_bf16(float* d, const uint32_t* a,
                                         const uint32_t* b) {
    asm volatile(
        "mma.sync.aligned.m16n8k16.row.col.f32.bf16.bf16.f32 "
        "{%0,%1,%2,%3}, {%4,%5,%6,%7}, {%8,%9}, {%0,%1,%2,%3};"
        : "+f"(d[0]), "+f"(d[1]), "+f"(d[2]), "+f"(d[3])
        : "r"(a[0]), "r"(a[1]), "r"(a[2]), "r"(a[3]), "r"(b[0]), "r"(b[1]));
}

// =====================================================================
// split_bf16: v -> hi = bf16(v), lo = bf16(v - hi)
// =====================================================================
__global__ void split_bf16(const float* __restrict__ src,
                           __nv_bfloat16* __restrict__ hi,
                           __nv_bfloat16* __restrict__ lo,
                           size_t n)
{
    size_t i = (size_t)blockIdx.x * blockDim.x + threadIdx.x;
    const size_t stride = (size_t)gridDim.x * blockDim.x;
    for (; i < n; i += stride) {
        const float v = src[i];
        const __nv_bfloat16 h = __float2bfloat16_rn(v);
        const float r = v - __bfloat162float(h);
        hi[i] = h;
        lo[i] = __float2bfloat16_rn(r);
    }
}

// =====================================================================
// gemm_mma: C[M,2048] = (Ahi+Alo)[M,K] @ (Whi+Wlo)[2048,K]^T + b1 + b2
// 3 bf16 mma passes: hi*hi + hi*lo + lo*hi, fp32 register accumulators.
// CTA 128x128, BK=32; 8 warps = 2(m) x 4(n); warp tile 64x32.
// smem rows 64B, chunk swizzle c^=(row>>1)&3 -> conflict-free ldmatrix.
// =====================================================================
__global__ __launch_bounds__(256, 2)
void gemm_mma(const __nv_bfloat16* __restrict__ Ahi,
              const __nv_bfloat16* __restrict__ Alo,
              const __nv_bfloat16* __restrict__ Whi,
              const __nv_bfloat16* __restrict__ Wlo,
              const float* __restrict__ b1, const float* __restrict__ b2,
              float* __restrict__ C, int K)
{
    __shared__ alignas(128) char sT[4][8192];   // Ahi, Alo, Whi, Wlo tiles
    __shared__ float bias_sm[128];

    const int tid  = threadIdx.x;
    const int wid  = tid >> 5;
    const int lane = tid & 31;
    const int bm   = blockIdx.y * 128;
    const int bn   = blockIdx.x * 128;
    const int wm   = wid & 1;                   // 0..1 -> 64 m-rows
    const int wn   = wid >> 1;                  // 0..3 -> 32 n-cols

    if (tid < 128) bias_sm[tid] = b1[bn + tid] + b2[bn + tid];

    // per-lane ldmatrix geometry
    const int q   = lane >> 3;
    const int rA  = (q & 1) * 8 + (lane & 7);   // A: quads [m0k0 m8k0 m0k8 m8k8]
    const int caA = q >> 1;
    const int sa  = (rA >> 1) & 3;
    const int rB  = (q >> 1) * 8 + (lane & 7);  // B: quads [n0k0 n0k8 n8k0 n8k8]
    const int cbB = q & 1;
    const int sb  = (rB >> 1) & 3;

    const uint32_t smem0 = s2u(sT);
    const uint32_t aRowB = (uint32_t)(wm * 64 + rA) * 64;
    const uint32_t bRowB = (uint32_t)(wn * 32 + rB) * 64;
    uint32_t aCk[2], bCk[2];
#pragma unroll
    for (int k = 0; k < 2; k++) {
        aCk[k] = (uint32_t)((((k << 1) + caA) ^ sa) * 16);
        bCk[k] = (uint32_t)((((k << 1) + cbB) ^ sb) * 16);
    }

    // gmem->smem geometry: thread = (row = tid>>2 [+64], chunk = tid&3)
    const int lrow = tid >> 2;
    const int lch  = tid & 3;
    uint32_t stOff[2];
#pragma unroll
    for (int r = 0; r < 2; r++) {
        const int row = lrow + r * 64;
        stOff[r] = (uint32_t)(row * 64 + ((lch ^ ((row >> 1) & 3)) * 16));
    }
    const __nv_bfloat16* src[4][2];
#pragma unroll
    for (int r = 0; r < 2; r++) {
        src[0][r] = Ahi + (size_t)(bm + lrow + 64 * r) * K + lch * 8;
        src[1][r] = Alo + (size_t)(bm + lrow + 64 * r) * K + lch * 8;
        src[2][r] = Whi + (size_t)(bn + lrow + 64 * r) * K + lch * 8;
        src[3][r] = Wlo + (size_t)(bn + lrow + 64 * r) * K + lch * 8;
    }

    float acc[4][4][4];
#pragma unroll
    for (int i = 0; i < 4; i++)
#pragma unroll
        for (int j = 0; j < 4; j++)
#pragma unroll
            for (int e = 0; e < 4; e++) acc[i][j][e] = 0.0f;

    for (int kt = 0; kt < K; kt += 32) {
        __syncthreads();                        // previous compute done
#pragma unroll
        for (int t = 0; t < 4; t++)
#pragma unroll
            for (int r = 0; r < 2; r++)
                *reinterpret_cast<uint4*>(sT[t] + stOff[r]) =
                    *reinterpret_cast<const uint4*>(src[t][r] + kt);
        __syncthreads();

#pragma unroll
        for (int kx = 0; kx < 2; kx++) {        // two k16 steps per BK
            uint32_t ah[16], wh[8], wl[8], al[16];
#pragma unroll
            for (int fm = 0; fm < 4; fm++)
                ldsm4(&ah[fm * 4], smem0 + 0 * 8192 + aRowB + fm * 1024 + aCk[kx]);
#pragma unroll
            for (int fp = 0; fp < 2; fp++)
                ldsm4(&wh[fp * 4], smem0 + 2 * 8192 + bRowB + fp * 1024 + bCk[kx]);
#pragma unroll
            for (int fm = 0; fm < 4; fm++)
#pragma unroll
                for (int fn = 0; fn < 4; fn++)
                    mma_bf16(acc[fm][fn], &ah[fm * 4], &wh[fn * 2]);   // hi*hi
#pragma unroll
            for (int fp = 0; fp < 2; fp++)
                ldsm4(&wl[fp * 4], smem0 + 3 * 8192 + bRowB + fp * 1024 + bCk[kx]);
#pragma unroll
            for (int fm = 0; fm < 4; fm++)
#pragma unroll
                for (int fn = 0; fn < 4; fn++)
                    mma_bf16(acc[fm][fn], &ah[fm * 4], &wl[fn * 2]);   // hi*lo
#pragma unroll
            for (int fm = 0; fm < 4; fm++)
                ldsm4(&al[fm * 4], smem0 + 1 * 8192 + aRowB + fm * 1024 + aCk[kx]);
#pragma unroll
            for (int fm = 0; fm < 4; fm++)
#pragma unroll
                for (int fn = 0; fn < 4; fn++)
                    mma_bf16(acc[fm][fn], &al[fm * 4], &wh[fn * 2]);   // lo*hi
        }
    }

    // epilogue: d0,d1 -> row lane/4; d2,d3 -> row+8; cols (lane&3)*2
#pragma unroll
    for (int fm = 0; fm < 4; fm++) {
        const int m0 = bm + wm * 64 + fm * 16 + (lane >> 2);
#pragma unroll
        for (int fn = 0; fn < 4; fn++) {
            const int c0 = wn * 32 + fn * 8 + (lane & 3) * 2;
            float2 v0, v1;
            v0.x = acc[fm][fn][0] + bias_sm[c0];
            v0.y = acc[fm][fn][1] + bias_sm[c0 + 1];
            v1.x = acc[fm][fn][2] + bias_sm[c0];
            v1.y = acc[fm][fn][3] + bias_sm[c0 + 1];
            *(float2*)&C[(size_t)m0 * G4 + bn + c0] = v0;
            *(float2*)&C[(size_t)(m0 + 8) * G4 + bn + c0] = v1;
        }
    }
}

// =====================================================================
// init_state
// =====================================================================
__global__ void init_state()
{
    const int i = blockIdx.x * blockDim.x + threadIdx.x;
    if (i < BATCH * HID) {
        g_h[0][0][i] = 0.0f; g_h[0][1][i] = 0.0f;
        g_h[1][0][i] = 0.0f; g_h[1][1][i] = 0.0f;
    }
    if (i < 4) { g_cnt_leaf[0][i] = 0u; g_cnt_leaf[1][i] = 0u; }
    if (i < 2) { g_cnt_root[i] = 0u; g_gen[i] = 0u; }
}

// =====================================================================
// Per-direction tree barrier (scoped acq/rel atomics)
// =====================================================================
__device__ __forceinline__ void dir_barrier(int dir, int bx)
{
    __syncthreads();
    if (threadIdx.x == 0) {
        unsigned* gen_p = &g_gen[dir];
        const unsigned gen = ld_acq(gen_p);
        const int g = (bx & 63) >> 4;
        if (atom_add_acqrel(&g_cnt_leaf[dir][g], 1u) == 15u) {
            st_rlx(&g_cnt_leaf[dir][g], 0u);
            if (atom_add_acqrel(&g_cnt_root[dir], 1u) == 3u) {
                st_rlx(&g_cnt_root[dir], 0u);
                st_rel(gen_p, gen + 1u);
            } else {
                while (ld_acq(gen_p) == gen) { }
            }
        } else {
            while (ld_acq(gen_p) == gen) { }
        }
    }
    __syncthreads();
}

// =====================================================================
// Persistent recurrence (round-6 passing version, unchanged)
// =====================================================================
__global__ __launch_bounds__(256) void lstm_persist(
    const float* __restrict__ xg_f, const float* __restrict__ xg_b,
    const float* __restrict__ whh_f, const float* __restrict__ whh_b,
    float* __restrict__ out)
{
    extern __shared__ float sm[];
    float (*wsm)[W_STRIDE] = (float(*)[W_STRIDE])sm;
    float (*hsm)[W_STRIDE] = (float(*)[W_STRIDE])(sm + 32 * W_STRIDE);
    float* psm = sm + 96 * W_STRIDE;

    const int tid = threadIdx.x;
    const int bx  = blockIdx.x;
    const int dir = bx >> 6;
    const int hb  = bx & 63;
    const int u0  = hb * 8;
    const int u   = tid & 7;
    const int bq  = (tid >> 3) & 15;
    const int kh  = tid >> 7;
    const int kb  = kh << 8;
    const int uu  = u0 + u;
    const int pidx = (bq * 8 + u) * PSM_STRIDE;

    const float* xg  = dir ? xg_b : xg_f;
    const float* whh = dir ? whh_b : whh_f;

    for (int i = tid; i < 32 * 128; i += 256) {
        const int rr = i >> 7;
        const int c  = (i & 127) << 2;
        const int grow = (rr >> 3) * HID + u0 + (rr & 7);
        *(float4*)&wsm[rr][c] = *(const float4*)&whh[(size_t)grow * HID + c];
    }
    __syncthreads();

    float cp[4] = {0.0f, 0.0f, 0.0f, 0.0f};

    for (int t = 0; t < T_LEN; t++) {
        const int t_eff = dir ? (T_LEN - 1 - t) : t;
        const int ping  = t & 1;
        const float* hprev = g_h[dir][ping];
        float*       hnext = g_h[dir][ping ^ 1];

        float xr[4][4];
        if (kh == 0) {
#pragma unroll
            for (int j = 0; j < 4; j++) {
                const int b = bq + j * 16;
#pragma unroll
                for (int g = 0; g < 4; g++)
                    xr[j][g] = __ldg(&xg[((size_t)t_eff * BATCH + b) * G4 + g * HID + uu]);
            }
        }

#pragma unroll
        for (int rr = 0; rr < 4; rr++) {
            float4 v[8];
#pragma unroll
            for (int r = 0; r < 8; r++) {
                const int idx = tid + (rr * 8 + r) * 256;
                v[r] = __ldcg((const float4*)&hprev[idx * 4]);
            }
#pragma unroll
            for (int r = 0; r < 8; r++) {
                const int idx = tid + (rr * 8 + r) * 256;
                *(float4*)&hsm[idx >> 7][(idx & 127) << 2] = v[r];
            }
        }
        __syncthreads();

        ull acc[4][4];
#pragma unroll
        for (int j = 0; j < 4; j++)
#pragma unroll
            for (int g = 0; g < 4; g++) acc[j][g] = 0ULL;

        ulonglong2 hn[4], wn[4];
#pragma unroll
        for (int j = 0; j < 4; j++)
            hn[j] = *(const ulonglong2*)&hsm[bq + j * 16][kb];
#pragma unroll
        for (int g = 0; g < 4; g++)
            wn[g] = *(const ulonglong2*)&wsm[g * 8 + u][kb];

#pragma unroll 2
        for (int k4 = 0; k4 < 64; k4++) {
            const ulonglong2 h0 = hn[0], h1 = hn[1], h2 = hn[2], h3 = hn[3];
            const ulonglong2 w0 = wn[0], w1 = wn[1], w2 = wn[2], w3 = wn[3];
            const int kn = kb + (k4 + 1) * 4;
            hn[0] = *(const ulonglong2*)&hsm[bq +  0][kn];
            hn[1] = *(const ulonglong2*)&hsm[bq + 16][kn];
            hn[2] = *(const ulonglong2*)&hsm[bq + 32][kn];
            hn[3] = *(const ulonglong2*)&hsm[bq + 48][kn];
            wn[0] = *(const ulonglong2*)&wsm[0 * 8 + u][kn];
            wn[1] = *(const ulonglong2*)&wsm[1 * 8 + u][kn];
            wn[2] = *(const ulonglong2*)&wsm[2 * 8 + u][kn];
            wn[3] = *(const ulonglong2*)&wsm[3 * 8 + u][kn];
            acc[0][0] = ffma2(h0.x, w0.x, acc[0][0]);
            acc[1][0] = ffma2(h1.x, w0.x, acc[1][0]);
            acc[2][0] = ffma2(h2.x, w0.x, acc[2][0]);
            acc[3][0] = ffma2(h3.x, w0.x, acc[3][0]);
            acc[0][1] = ffma2(h0.x, w1.x, acc[0][1]);
            acc[1][1] = ffma2(h1.x, w1.x, acc[1][1]);
            acc[2][1] = ffma2(h2.x, w1.x, acc[2][1]);
            acc[3][1] = ffma2(h3.x, w1.x, acc[3][1]);
            acc[0][2] = ffma2(h0.x, w2.x, acc[0][2]);
            acc[1][2] = ffma2(h1.x, w2.x, acc[1][2]);
            acc[2][2] = ffma2(h2.x, w2.x, acc[2][2]);
            acc[3][2] = ffma2(h3.x, w2.x, acc[3][2]);
            acc[0][3] = ffma2(h0.x, w3.x, acc[0][3]);
            acc[1][3] = ffma2(h1.x, w3.x, acc[1][3]);
            acc[2][3] = ffma2(h2.x, w3.x, acc[2][3]);
            acc[3][3] = ffma2(h3.x, w3.x, acc[3][3]);
            acc[0][0] = ffma2(h0.y, w0.y, acc[0][0]);
            acc[1][0] = ffma2(h1.y, w0.y, acc[1][0]);
            acc[2][0] = ffma2(h2.y, w0.y, acc[2][0]);
            acc[3][0] = ffma2(h3.y, w0.y, acc[3][0]);
            acc[0][1] = ffma2(h0.y, w1.y, acc[0][1]);
            acc[1][1] = ffma2(h1.y, w1.y, acc[1][1]);
            acc[2][1] = ffma2(h2.y, w1.y, acc[2][1]);
            acc[3][1] = ffma2(h3.y, w1.y, acc[3][1]);
            acc[0][2] = ffma2(h0.y, w2.y, acc[0][2]);
            acc[1][2] = ffma2(h1.y, w2.y, acc[1][2]);
            acc[2][2] = ffma2(h2.y, w2.y, acc[2][2]);
            acc[3][2] = ffma2(h3.y, w2.y, acc[3][2]);
            acc[0][3] = ffma2(h0.y, w3.y, acc[0][3]);
            acc[1][3] = ffma2(h1.y, w3.y, acc[1][3]);
            acc[2][3] = ffma2(h2.y, w3.y, acc[2][3]);
            acc[3][3] = ffma2(h3.y, w3.y, acc[3][3]);
        }

        float s[4][4];
#pragma unroll
        for (int j = 0; j < 4; j++)
#pragma unroll
            for (int g = 0; g < 4; g++) {
                const float2 v = unpk(acc[j][g]);
                s[j][g] = v.x + v.y;
            }

        if (kh == 1) {
#pragma unroll
            for (int j = 0; j < 4; j++)
                *(float4*)&psm[pidx + j * 4] =
                    make_float4(s[j][0], s[j][1], s[j][2], s[j][3]);
        }
        __syncthreads();

        if (kh == 0) {
#pragma unroll
            for (int j = 0; j < 4; j++) {
                const int b = bq + j * 16;
                const float4 p = *(const float4*)&psm[pidx + j * 4];
                const float gi = s[j][0] + p.x + xr[j][0];
                const float gf = s[j][1] + p.y + xr[j][1];
                const float gg = s[j][2] + p.z + xr[j][2];
                const float go = s[j][3] + p.w + xr[j][3];
                cp[j] = sigf(gf) * cp[j] + sigf(gi) * tanhf(gg);
                const float hv = sigf(go) * tanhf(cp[j]);
                __stcg(&hnext[b * HID + uu], hv);
                out[((size_t)t_eff * BATCH + b) * (2 * HID) + dir * HID + uu] = hv;
            }
        }

        dir_barrier(dir, bx);
    }
}

// =====================================================================
// host
// =====================================================================
extern "C" void kernel_launch(void* const* d_in, const int* in_sizes, int n_in,
                              void* d_out, int out_size)
{
    const float* x       = (const float*)d_in[0];
    const float* w_ih0_f = (const float*)d_in[1];
    const float* w_hh0_f = (const float*)d_in[2];
    const float* b_ih0_f = (const float*)d_in[3];
    const float* b_hh0_f = (const float*)d_in[4];
    const float* w_ih0_b = (const float*)d_in[5];
    const float* w_hh0_b = (const float*)d_in[6];
    const float* b_ih0_b = (const float*)d_in[7];
    const float* b_hh0_b = (const float*)d_in[8];
    const float* w_ih1_f = (const float*)d_in[9];
    const float* w_hh1_f = (const float*)d_in[10];
    const float* b_ih1_f = (const float*)d_in[11];
    const float* b_hh1_f = (const float*)d_in[12];
    const float* w_ih1_b = (const float*)d_in[13];
    const float* w_hh1_b = (const float*)d_in[14];
    const float* b_ih1_b = (const float*)d_in[15];
    const float* b_hh1_b = (const float*)d_in[16];
    float* out = (float*)d_out;

    float *xg_f, *xg_b, *l0;
    __nv_bfloat16 *a_hi, *a_lo, *whi_f, *wlo_f, *whi_b, *wlo_b;
    cudaGetSymbolAddress((void**)&xg_f,  g_xg_f);
    cudaGetSymbolAddress((void**)&xg_b,  g_xg_b);
    cudaGetSymbolAddress((void**)&l0,    g_l0);
    cudaGetSymbolAddress((void**)&a_hi,  g_a_hi);
    cudaGetSymbolAddress((void**)&a_lo,  g_a_lo);
    cudaGetSymbolAddress((void**)&whi_f, g_whi_f);
    cudaGetSymbolAddress((void**)&wlo_f, g_wlo_f);
    cudaGetSymbolAddress((void**)&whi_b, g_whi_b);
    cudaGetSymbolAddress((void**)&wlo_b, g_wlo_b);

    cudaFuncSetAttribute(lstm_persist,
                         cudaFuncAttributeMaxDynamicSharedMemorySize, SMEM_BYTES);

    const dim3 gemm_grid(G4 / 128, MROWS / 128);   // (16, 256)

    // ---- layer 0: split + mma GEMMs (K=512) ----
    split_bf16<<<512, 256>>>(x,       a_hi,  a_lo,  (size_t)MROWS * 512);
    split_bf16<<<256, 256>>>(w_ih0_f, whi_f, wlo_f, (size_t)G4 * 512);
    split_bf16<<<256, 256>>>(w_ih0_b, whi_b, wlo_b, (size_t)G4 * 512);
    gemm_mma<<<gemm_grid, 256>>>(a_hi, a_lo, whi_f, wlo_f, b_ih0_f, b_hh0_f, xg_f, 512);
    gemm_mma<<<gemm_grid, 256>>>(a_hi, a_lo, whi_b, wlo_b, b_ih0_b, b_hh0_b, xg_b, 512);
    init_state<<<128, 256>>>();
    lstm_persist<<<NBLK, 256, SMEM_BYTES>>>(xg_f, xg_b, w_hh0_f, w_hh0_b, l0);

    // ---- layer 1: split + mma GEMMs (K=1024) ----
    split_bf16<<<512, 256>>>(l0,      a_hi,  a_lo,  (size_t)MROWS * 1024);
    split_bf16<<<256, 256>>>(w_ih1_f, whi_f, wlo_f, (size_t)G4 * 1024);
    split_bf16<<<256, 256>>>(w_ih1_b, whi_b, wlo_b, (size_t)G4 * 1024);
    gemm_mma<<<gemm_grid, 256>>>(a_hi, a_lo, whi_f, wlo_f, b_ih1_f, b_hh1_f, xg_f, 1024);
    gemm_mma<<<gemm_grid, 256>>>(a_hi, a_lo, whi_b, wlo_b, b_ih1_b, b_hh1_b, xg_b, 1024);
    init_state<<<128, 256>>>();
    lstm_persist<<<NBLK, 256, SMEM_BYTES>>>(xg_f, xg_b, w_hh1_f, w_hh1_b, out);
}

// round 10
// speedup vs baseline: 2.2773x; 1.4641x over previous
#include <cuda_runtime.h>
#include <cuda_bf16.h>
#include <cstdint>
#include <math.h>

// LSTM_38646115729591 — 2-layer bidirectional LSTM.
// T=512, B=64, D=512, H=512. Output [T,B,2H] fp32.
// Input GEMMs: mma.sync bf16, 2-term hi/lo split (round-9 passing version).
// Recurrence: persistent mma.sync bf16 kernel, same 3-term split numerics.

#define T_LEN 512
#define BATCH 64
#define HID   512
#define G4    2048
#define MROWS (T_LEN * BATCH)   // 32768
#define NBLK  128

// recurrence smem layout (bytes)
#define OFF_WHI 0
#define OFF_WLO 32768
#define OFF_HHI 65536
#define OFF_HLO 131072
#define OFF_PSM 196608
#define RSMEM_BYTES (196608 + 8192)   // 204800

typedef unsigned long long ull;

// ---- static device scratch ----
__device__ float g_xg_f[(size_t)MROWS * G4];
__device__ float g_xg_b[(size_t)MROWS * G4];
__device__ float g_l0[(size_t)MROWS * 2 * HID];
__device__ __nv_bfloat16 g_hbf[2][2][2][BATCH * HID];  // [dir][ping][hi/lo]
__device__ unsigned g_cnt_leaf[2][4];
__device__ unsigned g_cnt_root[2];
__device__ unsigned g_gen[2];

__device__ __nv_bfloat16 g_a_hi[(size_t)MROWS * 1024];
__device__ __nv_bfloat16 g_a_lo[(size_t)MROWS * 1024];
__device__ __nv_bfloat16 g_whi_f[(size_t)G4 * 1024];
__device__ __nv_bfloat16 g_wlo_f[(size_t)G4 * 1024];
__device__ __nv_bfloat16 g_whi_b[(size_t)G4 * 1024];
__device__ __nv_bfloat16 g_wlo_b[(size_t)G4 * 1024];

__device__ __forceinline__ float sigf(float x) { return 1.0f / (1.0f + __expf(-x)); }

// ---- scoped sync primitives ----
__device__ __forceinline__ unsigned atom_add_acqrel(unsigned* p, unsigned v) {
    unsigned old;
    asm volatile("atom.add.acq_rel.gpu.u32 %0, [%1], %2;"
                 : "=r"(old) : "l"(p), "r"(v) : "memory");
    return old;
}
__device__ __forceinline__ unsigned ld_acq(const unsigned* p) {
    unsigned v;
    asm volatile("ld.acquire.gpu.u32 %0, [%1];" : "=r"(v) : "l"(p) : "memory");
    return v;
}
__device__ __forceinline__ void st_rel(unsigned* p, unsigned v) {
    asm volatile("st.release.gpu.u32 [%0], %1;" :: "l"(p), "r"(v) : "memory");
}
__device__ __forceinline__ void st_rlx(unsigned* p, unsigned v) {
    asm volatile("st.relaxed.gpu.u32 [%0], %1;" :: "l"(p), "r"(v) : "memory");
}

// ---- mma.sync helpers (sm_80 baseline PTX — valid on compute_103) ----
__device__ __forceinline__ uint32_t s2u(const void* p) {
    return (uint32_t)__cvta_generic_to_shared(p);
}
__device__ __forceinline__ void ldsm4(uint32_t* r, uint32_t addr) {
    asm volatile(
        "ldmatrix.sync.aligned.m8n8.x4.shared.b16 {%0,%1,%2,%3}, [%4];"
        : "=r"(r[0]), "=r"(r[1]), "=r"(r[2]), "=r"(r[3]) : "r"(addr));
}
__device__ __forceinline__ void mma_bf16(float* d, const uint32_t* a,
                                         const uint32_t* b) {
    asm volatile(
        "mma.sync.aligned.m16n8k16.row.col.f32.bf16.bf16.f32 "
        "{%0,%1,%2,%3}, {%4,%5,%6,%7}, {%8,%9}, {%0,%1,%2,%3};"
        : "+f"(d[0]), "+f"(d[1]), "+f"(d[2]), "+f"(d[3])
        : "r"(a[0]), "r"(a[1]), "r"(a[2]), "r"(a[3]), "r"(b[0]), "r"(b[1]));
}
// split two floats into packed bf16 hi-pair and lo-pair (residual)
__device__ __forceinline__ void split2(float a, float b,
                                       unsigned& h, unsigned& l) {
    const __nv_bfloat16 ha = __float2bfloat16_rn(a);
    const __nv_bfloat16 hb = __float2bfloat16_rn(b);
    const float ra = a - __bfloat162float(ha);
    const float rb = b - __bfloat162float(hb);
    h = (unsigned)__bfloat16_as_ushort(ha)
      | ((unsigned)__bfloat16_as_ushort(hb) << 16);
    l = (unsigned)__bfloat16_as_ushort(__float2bfloat16_rn(ra))
      | ((unsigned)__bfloat16_as_ushort(__float2bfloat16_rn(rb)) << 16);
}

// =====================================================================
// split_bf16: v -> hi = bf16(v), lo = bf16(v - hi)
// =====================================================================
__global__ void split_bf16(const float* __restrict__ src,
                           __nv_bfloat16* __restrict__ hi,
                           __nv_bfloat16* __restrict__ lo,
                           size_t n)
{
    size_t i = (size_t)blockIdx.x * blockDim.x + threadIdx.x;
    const size_t stride = (size_t)gridDim.x * blockDim.x;
    for (; i < n; i += stride) {
        const float v = src[i];
        const __nv_bfloat16 h = __float2bfloat16_rn(v);
        const float r = v - __bfloat162float(h);
        hi[i] = h;
        lo[i] = __float2bfloat16_rn(r);
    }
}

// =====================================================================
// gemm_mma (round-9 passing version, unchanged)
// =====================================================================
__global__ __launch_bounds__(256, 2)
void gemm_mma(const __nv_bfloat16* __restrict__ Ahi,
              const __nv_bfloat16* __restrict__ Alo,
              const __nv_bfloat16* __restrict__ Whi,
              const __nv_bfloat16* __restrict__ Wlo,
              const float* __restrict__ b1, const float* __restrict__ b2,
              float* __restrict__ C, int K)
{
    __shared__ alignas(128) char sT[4][8192];
    __shared__ float bias_sm[128];

    const int tid  = threadIdx.x;
    const int wid  = tid >> 5;
    const int lane = tid & 31;
    const int bm   = blockIdx.y * 128;
    const int bn   = blockIdx.x * 128;
    const int wm   = wid & 1;
    const int wn   = wid >> 1;

    if (tid < 128) bias_sm[tid] = b1[bn + tid] + b2[bn + tid];

    const int q   = lane >> 3;
    const int rA  = (q & 1) * 8 + (lane & 7);
    const int caA = q >> 1;
    const int sa  = (rA >> 1) & 3;
    const int rB  = (q >> 1) * 8 + (lane & 7);
    const int cbB = q & 1;
    const int sb  = (rB >> 1) & 3;

    const uint32_t smem0 = s2u(sT);
    const uint32_t aRowB = (uint32_t)(wm * 64 + rA) * 64;
    const uint32_t bRowB = (uint32_t)(wn * 32 + rB) * 64;
    uint32_t aCk[2], bCk[2];
#pragma unroll
    for (int k = 0; k < 2; k++) {
        aCk[k] = (uint32_t)((((k << 1) + caA) ^ sa) * 16);
        bCk[k] = (uint32_t)((((k << 1) + cbB) ^ sb) * 16);
    }

    const int lrow = tid >> 2;
    const int lch  = tid & 3;
    uint32_t stOff[2];
#pragma unroll
    for (int r = 0; r < 2; r++) {
        const int row = lrow + r * 64;
        stOff[r] = (uint32_t)(row * 64 + ((lch ^ ((row >> 1) & 3)) * 16));
    }
    const __nv_bfloat16* src[4][2];
#pragma unroll
    for (int r = 0; r < 2; r++) {
        src[0][r] = Ahi + (size_t)(bm + lrow + 64 * r) * K + lch * 8;
        src[1][r] = Alo + (size_t)(bm + lrow + 64 * r) * K + lch * 8;
        src[2][r] = Whi + (size_t)(bn + lrow + 64 * r) * K + lch * 8;
        src[3][r] = Wlo + (size_t)(bn + lrow + 64 * r) * K + lch * 8;
    }

    float acc[4][4][4];
#pragma unroll
    for (int i = 0; i < 4; i++)
#pragma unroll
        for (int j = 0; j < 4; j++)
#pragma unroll
            for (int e = 0; e < 4; e++) acc[i][j][e] = 0.0f;

    for (int kt = 0; kt < K; kt += 32) {
        __syncthreads();
#pragma unroll
        for (int t = 0; t < 4; t++)
#pragma unroll
            for (int r = 0; r < 2; r++)
                *reinterpret_cast<uint4*>(sT[t] + stOff[r]) =
                    *reinterpret_cast<const uint4*>(src[t][r] + kt);
        __syncthreads();

#pragma unroll
        for (int kx = 0; kx < 2; kx++) {
            uint32_t ah[16], wh[8], wl[8], al[16];
#pragma unroll
            for (int fm = 0; fm < 4; fm++)
                ldsm4(&ah[fm * 4], smem0 + 0 * 8192 + aRowB + fm * 1024 + aCk[kx]);
#pragma unroll
            for (int fp = 0; fp < 2; fp++)
                ldsm4(&wh[fp * 4], smem0 + 2 * 8192 + bRowB + fp * 1024 + bCk[kx]);
#pragma unroll
            for (int fm = 0; fm < 4; fm++)
#pragma unroll
                for (int fn = 0; fn < 4; fn++)
                    mma_bf16(acc[fm][fn], &ah[fm * 4], &wh[fn * 2]);
#pragma unroll
            for (int fp = 0; fp < 2; fp++)
                ldsm4(&wl[fp * 4], smem0 + 3 * 8192 + bRowB + fp * 1024 + bCk[kx]);
#pragma unroll
            for (int fm = 0; fm < 4; fm++)
#pragma unroll
                for (int fn = 0; fn < 4; fn++)
                    mma_bf16(acc[fm][fn], &ah[fm * 4], &wl[fn * 2]);
#pragma unroll
            for (int fm = 0; fm < 4; fm++)
                ldsm4(&al[fm * 4], smem0 + 1 * 8192 + aRowB + fm * 1024 + aCk[kx]);
#pragma unroll
            for (int fm = 0; fm < 4; fm++)
#pragma unroll
                for (int fn = 0; fn < 4; fn++)
                    mma_bf16(acc[fm][fn], &al[fm * 4], &wh[fn * 2]);
        }
    }

#pragma unroll
    for (int fm = 0; fm < 4; fm++) {
        const int m0 = bm + wm * 64 + fm * 16 + (lane >> 2);
#pragma unroll
        for (int fn = 0; fn < 4; fn++) {
            const int c0 = wn * 32 + fn * 8 + (lane & 3) * 2;
            float2 v0, v1;
            v0.x = acc[fm][fn][0] + bias_sm[c0];
            v0.y = acc[fm][fn][1] + bias_sm[c0 + 1];
            v1.x = acc[fm][fn][2] + bias_sm[c0];
            v1.y = acc[fm][fn][3] + bias_sm[c0 + 1];
            *(float2*)&C[(size_t)m0 * G4 + bn + c0] = v0;
            *(float2*)&C[(size_t)(m0 + 8) * G4 + bn + c0] = v1;
        }
    }
}

// =====================================================================
// init_state: zero bf16 h ping-pong planes + barrier state
// =====================================================================
__global__ void init_state()
{
    const int i = blockIdx.x * blockDim.x + threadIdx.x;   // 65536 threads
    unsigned* p = (unsigned*)g_hbf;                        // 131072 words
    for (int k = i; k < 131072; k += 65536) p[k] = 0u;
    if (i < 4) { g_cnt_leaf[0][i] = 0u; g_cnt_leaf[1][i] = 0u; }
    if (i < 2) { g_cnt_root[i] = 0u; g_gen[i] = 0u; }
}

// =====================================================================
// Per-direction tree barrier (scoped acq/rel atomics)
// =====================================================================
__device__ __forceinline__ void dir_barrier(int dir, int bx)
{
    __syncthreads();
    if (threadIdx.x == 0) {
        unsigned* gen_p = &g_gen[dir];
        const unsigned gen = ld_acq(gen_p);
        const int g = (bx & 63) >> 4;
        if (atom_add_acqrel(&g_cnt_leaf[dir][g], 1u) == 15u) {
            st_rlx(&g_cnt_leaf[dir][g], 0u);
            if (atom_add_acqrel(&g_cnt_root[dir], 1u) == 3u) {
                st_rlx(&g_cnt_root[dir], 0u);
                st_rel(gen_p, gen + 1u);
            } else {
                while (ld_acq(gen_p) == gen) { }
            }
        } else {
            while (ld_acq(gen_p) == gen) { }
        }
    }
    __syncthreads();
}

// =====================================================================
// Persistent recurrence via mma.sync, 3-term bf16 split.
// 128 blocks x 256 thr: dir = bx/64, hb = bx%64 -> 32 W rows (n = g*8+j).
// Warps: wm = w&3 (16 batch rows), kh = w>>2 (K-half). Per k16 step:
// 6 ldmatrix + 12 mma (hi*Whi + hi*Wlo + lo*Whi into one fp32 acc).
// Lane owns all 4 gates of its (batch, unit) cells -> shuffle-free update.
// h ping-pong in global as split bf16 planes; W split resident in smem.
// =====================================================================
__global__ __launch_bounds__(256) void lstm_persist_mma(
    const float* __restrict__ xg_f, const float* __restrict__ xg_b,
    const float* __restrict__ whh_f, const float* __restrict__ whh_b,
    float* __restrict__ out)
{
    extern __shared__ char smc[];
    const uint32_t smem_u = s2u(smc);
    float* psm = (float*)(smc + OFF_PSM);

    const int tid  = threadIdx.x;
    const int bx   = blockIdx.x;
    const int dir  = bx >> 6;
    const int hb   = bx & 63;
    const int u0   = hb * 8;
    const int w    = tid >> 5;
    const int lane = tid & 31;
    const int wm   = w & 3;
    const int kh   = w >> 2;
    const int q    = lane >> 3;
    const int l7   = lane & 7;

    const float* xg  = dir ? xg_b : xg_f;
    const float* whh = dir ? whh_b : whh_f;

    // ---- one-time: split W slice (32 rows x 512) into smem bf16 hi/lo ----
    for (int ci = tid; ci < 32 * 64; ci += 256) {          // 16B chunks
        const int row = ci >> 6, c = ci & 63;
        const int grow = (row >> 3) * HID + u0 + (row & 7);
        const float4 f0 = __ldg((const float4*)&whh[(size_t)grow * HID + c * 8]);
        const float4 f1 = __ldg((const float4*)&whh[(size_t)grow * HID + c * 8 + 4]);
        unsigned h0, l0, h1, l1, h2, l2, h3, l3;
        split2(f0.x, f0.y, h0, l0); split2(f0.z, f0.w, h1, l1);
        split2(f1.x, f1.y, h2, l2); split2(f1.z, f1.w, h3, l3);
        const uint32_t dst = (uint32_t)(row * 1024 + ((c ^ (row & 7)) << 4));
        *(uint4*)(smc + OFF_WHI + dst) = make_uint4(h0, h1, h2, h3);
        *(uint4*)(smc + OFF_WLO + dst) = make_uint4(l0, l1, l2, l3);
    }
    __syncthreads();

    // ldmatrix lane geometry
    const int aRow = wm * 16 + (q & 1) * 8 + l7;           // A rows (batch)
    const int aSel = q >> 1;
    const int aXor = aRow & 7;
    const uint32_t aBase = (uint32_t)aRow * 1024;
    const int bRow = (q >> 1) * 8 + l7;                    // B rows (gates)
    const int bSel = q & 1;
    const int bXor = bRow & 7;                             // same for +16
    const uint32_t bBase0 = (uint32_t)bRow * 1024;
    const uint32_t bBase1 = (uint32_t)(bRow + 16) * 1024;

    const int m0 = wm * 16 + (lane >> 2);                  // epilogue cells
    const int j2 = (lane & 3) * 2;
    const int uu2 = u0 + j2;

    float cst[2][2] = {{0.0f, 0.0f}, {0.0f, 0.0f}};        // c-state (kh==0)
    const int kb16 = kh * 16;

    for (int t = 0; t < T_LEN; t++) {
        const int t_eff = dir ? (T_LEN - 1 - t) : t;
        const int ping  = t & 1;
        const __nv_bfloat16* hpH = &g_hbf[dir][ping][0][0];
        const __nv_bfloat16* hpL = &g_hbf[dir][ping][1][0];
        __nv_bfloat16* hnH = &g_hbf[dir][ping ^ 1][0][0];
        __nv_bfloat16* hnL = &g_hbf[dir][ping ^ 1][1][0];

        // prefetch xg gate rows (kh==0 lanes finalize)
        float2 xr[4][2];
        if (kh == 0) {
#pragma unroll
            for (int g = 0; g < 4; g++)
#pragma unroll
                for (int r = 0; r < 2; r++) {
                    const int b = m0 + r * 8;
                    xr[g][r] = __ldg((const float2*)
                        &xg[((size_t)t_eff * BATCH + b) * G4 + g * HID + uu2]);
                }
        }

        // ---- stage h hi/lo planes (64 x 512 bf16 each) with swizzle ----
#pragma unroll
        for (int it = 0; it < 16; it++) {
            const int ci = tid + it * 256;                 // 0..4095
            const int row = ci >> 6, c = ci & 63;
            const uint4 vh = __ldcg((const uint4*)(hpH + row * 512 + c * 8));
            const uint4 vl = __ldcg((const uint4*)(hpL + row * 512 + c * 8));
            const uint32_t dst = (uint32_t)(row * 1024 + ((c ^ (row & 7)) << 4));
            *(uint4*)(smc + OFF_HHI + dst) = vh;
            *(uint4*)(smc + OFF_HLO + dst) = vl;
        }
        __syncthreads();

        // ---- mma over this warp's K-half: 16 k16 steps ----
        float acc[4][4];
#pragma unroll
        for (int fn = 0; fn < 4; fn++)
#pragma unroll
            for (int e = 0; e < 4; e++) acc[fn][e] = 0.0f;

#pragma unroll
        for (int kk = 0; kk < 16; kk++) {
            const int s = kb16 + kk;
            const uint32_t ca = (uint32_t)(((2 * s + aSel) ^ aXor) << 4);
            const uint32_t cb = (uint32_t)(((2 * s + bSel) ^ bXor) << 4);
            uint32_t ahi[4], alo[4], w0h[4], w1h[4], w0l[4], w1l[4];
            ldsm4(ahi, smem_u + OFF_HHI + aBase + ca);
            ldsm4(w0h, smem_u + OFF_WHI + bBase0 + cb);
            ldsm4(w1h, smem_u + OFF_WHI + bBase1 + cb);
            ldsm4(w0l, smem_u + OFF_WLO + bBase0 + cb);
            ldsm4(w1l, smem_u + OFF_WLO + bBase1 + cb);
            ldsm4(alo, smem_u + OFF_HLO + aBase + ca);
            mma_bf16(acc[0], ahi, w0h + 0);
            mma_bf16(acc[1], ahi, w0h + 2);
            mma_bf16(acc[2], ahi, w1h + 0);
            mma_bf16(acc[3], ahi, w1h + 2);
            mma_bf16(acc[0], ahi, w0l + 0);
            mma_bf16(acc[1], ahi, w0l + 2);
            mma_bf16(acc[2], ahi, w1l + 0);
            mma_bf16(acc[3], ahi, w1l + 2);
            mma_bf16(acc[0], alo, w0h + 0);
            mma_bf16(acc[1], alo, w0h + 2);
            mma_bf16(acc[2], alo, w1h + 0);
            mma_bf16(acc[3], alo, w1h + 2);
        }

        // ---- K-half reduction ----
        if (kh == 1) {
            float* pp = psm + (wm * 32 + lane) * 16;
#pragma unroll
            for (int fn = 0; fn < 4; fn++)
#pragma unroll
                for (int e = 0; e < 4; e++) pp[fn * 4 + e] = acc[fn][e];
        }
        __syncthreads();

        if (kh == 0) {
            const float* pp = psm + (wm * 32 + lane) * 16;
#pragma unroll
            for (int fn = 0; fn < 4; fn++)
#pragma unroll
                for (int e = 0; e < 4; e++) acc[fn][e] += pp[fn * 4 + e];

#pragma unroll
            for (int r = 0; r < 2; r++) {
                const int b = m0 + r * 8;
                float hv[2];
#pragma unroll
                for (int cc = 0; cc < 2; cc++) {
                    const int e = r * 2 + cc;
                    const float gi = acc[0][e] + (cc ? xr[0][r].y : xr[0][r].x);
                    const float gf = acc[1][e] + (cc ? xr[1][r].y : xr[1][r].x);
                    const float gg = acc[2][e] + (cc ? xr[2][r].y : xr[2][r].x);
                    const float go = acc[3][e] + (cc ? xr[3][r].y : xr[3][r].x);
                    cst[r][cc] = sigf(gf) * cst[r][cc] + sigf(gi) * tanhf(gg);
                    hv[cc] = sigf(go) * tanhf(cst[r][cc]);
                }
                *(float2*)&out[((size_t)t_eff * BATCH + b) * (2 * HID)
                               + dir * HID + uu2] = make_float2(hv[0], hv[1]);
                unsigned ph, pl;
                split2(hv[0], hv[1], ph, pl);
                __stcg((unsigned*)(hnH + b * 512 + uu2), ph);
                __stcg((unsigned*)(hnL + b * 512 + uu2), pl);
            }
        }

        dir_barrier(dir, bx);
    }
}

// =====================================================================
// host
// =====================================================================
extern "C" void kernel_launch(void* const* d_in, const int* in_sizes, int n_in,
                              void* d_out, int out_size)
{
    const float* x       = (const float*)d_in[0];
    const float* w_ih0_f = (const float*)d_in[1];
    const float* w_hh0_f = (const float*)d_in[2];
    const float* b_ih0_f = (const float*)d_in[3];
    const float* b_hh0_f = (const float*)d_in[4];
    const float* w_ih0_b = (const float*)d_in[5];
    const float* w_hh0_b = (const float*)d_in[6];
    const float* b_ih0_b = (const float*)d_in[7];
    const float* b_hh0_b = (const float*)d_in[8];
    const float* w_ih1_f = (const float*)d_in[9];
    const float* w_hh1_f = (const float*)d_in[10];
    const float* b_ih1_f = (const float*)d_in[11];
    const float* b_hh1_f = (const float*)d_in[12];
    const float* w_ih1_b = (const float*)d_in[13];
    const float* w_hh1_b = (const float*)d_in[14];
    const float* b_ih1_b = (const float*)d_in[15];
    const float* b_hh1_b = (const float*)d_in[16];
    float* out = (float*)d_out;

    float *xg_f, *xg_b, *l0;
    __nv_bfloat16 *a_hi, *a_lo, *whi_f, *wlo_f, *whi_b, *wlo_b;
    cudaGetSymbolAddress((void**)&xg_f,  g_xg_f);
    cudaGetSymbolAddress((void**)&xg_b,  g_xg_b);
    cudaGetSymbolAddress((void**)&l0,    g_l0);
    cudaGetSymbolAddress((void**)&a_hi,  g_a_hi);
    cudaGetSymbolAddress((void**)&a_lo,  g_a_lo);
    cudaGetSymbolAddress((void**)&whi_f, g_whi_f);
    cudaGetSymbolAddress((void**)&wlo_f, g_wlo_f);
    cudaGetSymbolAddress((void**)&whi_b, g_whi_b);
    cudaGetSymbolAddress((void**)&wlo_b, g_wlo_b);

    cudaFuncSetAttribute(lstm_persist_mma,
                         cudaFuncAttributeMaxDynamicSharedMemorySize, RSMEM_BYTES);

    const dim3 gemm_grid(G4 / 128, MROWS / 128);   // (16, 256)

    // ---- layer 0: split + mma GEMMs (K=512) ----
    split_bf16<<<512, 256>>>(x,       a_hi,  a_lo,  (size_t)MROWS * 512);
    split_bf16<<<256, 256>>>(w_ih0_f, whi_f, wlo_f, (size_t)G4 * 512);
    split_bf16<<<256, 256>>>(w_ih0_b, whi_b, wlo_b, (size_t)G4 * 512);
    gemm_mma<<<gemm_grid, 256>>>(a_hi, a_lo, whi_f, wlo_f, b_ih0_f, b_hh0_f, xg_f, 512);
    gemm_mma<<<gemm_grid, 256>>>(a_hi, a_lo, whi_b, wlo_b, b_ih0_b, b_hh0_b, xg_b, 512);
    init_state<<<256, 256>>>();
    lstm_persist_mma<<<NBLK, 256, RSMEM_BYTES>>>(xg_f, xg_b, w_hh0_f, w_hh0_b, l0);

    // ---- layer 1: split + mma GEMMs (K=1024) ----
    split_bf16<<<512, 256>>>(l0,      a_hi,  a_lo,  (size_t)MROWS * 1024);
    split_bf16<<<256, 256>>>(w_ih1_f, whi_f, wlo_f, (size_t)G4 * 1024);
    split_bf16<<<256, 256>>>(w_ih1_b, whi_b, wlo_b, (size_t)G4 * 1024);
    gemm_mma<<<gemm_grid, 256>>>(a_hi, a_lo, whi_f, wlo_f, b_ih1_f, b_hh1_f, xg_f, 1024);
    gemm_mma<<<gemm_grid, 256>>>(a_hi, a_lo, whi_b, wlo_b, b_ih1_b, b_hh1_b, xg_b, 1024);
    init_state<<<256, 256>>>();
    lstm_persist_mma<<<NBLK, 256, RSMEM_BYTES>>>(xg_f, xg_b, w_hh1_f, w_hh1_b, out);
}

// round 11
// speedup vs baseline: 2.4368x; 1.0700x over previous
#include <cuda_runtime.h>
#include <cuda_bf16.h>
#include <cstdint>
#include <math.h>

// LSTM_38646115729591 — 2-layer bidirectional LSTM.
// T=512, B=64, D=512, H=512. Output [T,B,2H] fp32.
// Input GEMMs: mma.sync bf16, 2-term hi/lo split.
// Recurrence: persistent mma.sync bf16, 3-term split, cp.async staging.

#define T_LEN 512
#define BATCH 64
#define HID   512
#define G4    2048
#define MROWS (T_LEN * BATCH)   // 32768
#define NBLK  128

// recurrence smem layout (bytes)
#define OFF_WHI 0
#define OFF_WLO 32768
#define OFF_HHI 65536
#define OFF_HLO 131072
#define OFF_PSM 196608
#define RSMEM_BYTES (196608 + 8192)   // 204800

typedef unsigned long long ull;

// ---- static device scratch ----
__device__ float g_xg_f[(size_t)MROWS * G4];
__device__ float g_xg_b[(size_t)MROWS * G4];
__device__ float g_l0[(size_t)MROWS * 2 * HID];        // layer-0 out sink
__device__ __nv_bfloat16 g_hbf[2][2][2][BATCH * HID];  // [dir][ping][hi/lo]
__device__ unsigned g_cnt_leaf[2][4];
__device__ unsigned g_cnt_root[2];
__device__ unsigned g_gen[2];

__device__ __nv_bfloat16 g_a_hi[(size_t)MROWS * 1024];
__device__ __nv_bfloat16 g_a_lo[(size_t)MROWS * 1024];
__device__ __nv_bfloat16 g_whi_f[(size_t)G4 * 1024];
__device__ __nv_bfloat16 g_wlo_f[(size_t)G4 * 1024];
__device__ __nv_bfloat16 g_whi_b[(size_t)G4 * 1024];
__device__ __nv_bfloat16 g_wlo_b[(size_t)G4 * 1024];

__device__ __forceinline__ float sigf(float x) { return 1.0f / (1.0f + __expf(-x)); }

// ---- scoped sync primitives ----
__device__ __forceinline__ unsigned atom_add_acqrel(unsigned* p, unsigned v) {
    unsigned old;
    asm volatile("atom.add.acq_rel.gpu.u32 %0, [%1], %2;"
                 : "=r"(old) : "l"(p), "r"(v) : "memory");
    return old;
}
__device__ __forceinline__ unsigned ld_acq(const unsigned* p) {
    unsigned v;
    asm volatile("ld.acquire.gpu.u32 %0, [%1];" : "=r"(v) : "l"(p) : "memory");
    return v;
}
__device__ __forceinline__ void st_rel(unsigned* p, unsigned v) {
    asm volatile("st.release.gpu.u32 [%0], %1;" :: "l"(p), "r"(v) : "memory");
}
__device__ __forceinline__ void st_rlx(unsigned* p, unsigned v) {
    asm volatile("st.relaxed.gpu.u32 [%0], %1;" :: "l"(p), "r"(v) : "memory");
}

// ---- mma.sync / cp.async helpers (sm_80 PTX — valid on compute_103) ----
__device__ __forceinline__ uint32_t s2u(const void* p) {
    return (uint32_t)__cvta_generic_to_shared(p);
}
__device__ __forceinline__ void ldsm4(uint32_t* r, uint32_t addr) {
    asm volatile(
        "ldmatrix.sync.aligned.m8n8.x4.shared.b16 {%0,%1,%2,%3}, [%4];"
        : "=r"(r[0]), "=r"(r[1]), "=r"(r[2]), "=r"(r[3]) : "r"(addr));
}
__device__ __forceinline__ void mma_bf16(float* d, const uint32_t* a,
                                         const uint32_t* b) {
    asm volatile(
        "mma.sync.aligned.m16n8k16.row.col.f32.bf16.bf16.f32 "
        "{%0,%1,%2,%3}, {%4,%5,%6,%7}, {%8,%9}, {%0,%1,%2,%3};"
        : "+f"(d[0]), "+f"(d[1]), "+f"(d[2]), "+f"(d[3])
        : "r"(a[0]), "r"(a[1]), "r"(a[2]), "r"(a[3]), "r"(b[0]), "r"(b[1]));
}
__device__ __forceinline__ void cpa16(uint32_t smem_dst, const void* gsrc) {
    asm volatile("cp.async.cg.shared.global [%0], [%1], 16;"
                 :: "r"(smem_dst), "l"(__cvta_generic_to_global(gsrc))
                 : "memory");
}
__device__ __forceinline__ void cpa_commit_wait() {
    asm volatile("cp.async.commit_group;" ::: "memory");
    asm volatile("cp.async.wait_group 0;" ::: "memory");
}
// split two floats into packed bf16 hi-pair and lo-pair (residual)
__device__ __forceinline__ void split2(float a, float b,
                                       unsigned& h, unsigned& l) {
    const __nv_bfloat16 ha = __float2bfloat16_rn(a);
    const __nv_bfloat16 hb = __float2bfloat16_rn(b);
    const float ra = a - __bfloat162float(ha);
    const float rb = b - __bfloat162float(hb);
    h = (unsigned)__bfloat16_as_ushort(ha)
      | ((unsigned)__bfloat16_as_ushort(hb) << 16);
    l = (unsigned)__bfloat16_as_ushort(__float2bfloat16_rn(ra))
      | ((unsigned)__bfloat16_as_ushort(__float2bfloat16_rn(rb)) << 16);
}

// =====================================================================
// split_bf16: v -> hi = bf16(v), lo = bf16(v - hi)
// =====================================================================
__global__ void split_bf16(const float* __restrict__ src,
                           __nv_bfloat16* __restrict__ hi,
                           __nv_bfloat16* __restrict__ lo,
                           size_t n)
{
    size_t i = (size_t)blockIdx.x * blockDim.x + threadIdx.x;
    const size_t stride = (size_t)gridDim.x * blockDim.x;
    for (; i < n; i += stride) {
        const float v = src[i];
        const __nv_bfloat16 h = __float2bfloat16_rn(v);
        const float r = v - __bfloat162float(h);
        hi[i] = h;
        lo[i] = __float2bfloat16_rn(r);
    }
}

// =====================================================================
// gemm_mma (round-9/10 passing version, unchanged)
// =====================================================================
__global__ __launch_bounds__(256, 2)
void gemm_mma(const __nv_bfloat16* __restrict__ Ahi,
              const __nv_bfloat16* __restrict__ Alo,
              const __nv_bfloat16* __restrict__ Whi,
              const __nv_bfloat16* __restrict__ Wlo,
              const float* __restrict__ b1, const float* __restrict__ b2,
              float* __restrict__ C, int K)
{
    __shared__ alignas(128) char sT[4][8192];
    __shared__ float bias_sm[128];

    const int tid  = threadIdx.x;
    const int wid  = tid >> 5;
    const int lane = tid & 31;
    const int bm   = blockIdx.y * 128;
    const int bn   = blockIdx.x * 128;
    const int wm   = wid & 1;
    const int wn   = wid >> 1;

    if (tid < 128) bias_sm[tid] = b1[bn + tid] + b2[bn + tid];

    const int q   = lane >> 3;
    const int rA  = (q & 1) * 8 + (lane & 7);
    const int caA = q >> 1;
    const int sa  = (rA >> 1) & 3;
    const int rB  = (q >> 1) * 8 + (lane & 7);
    const int cbB = q & 1;
    const int sb  = (rB >> 1) & 3;

    const uint32_t smem0 = s2u(sT);
    const uint32_t aRowB = (uint32_t)(wm * 64 + rA) * 64;
    const uint32_t bRowB = (uint32_t)(wn * 32 + rB) * 64;
    uint32_t aCk[2], bCk[2];
#pragma unroll
    for (int k = 0; k < 2; k++) {
        aCk[k] = (uint32_t)((((k << 1) + caA) ^ sa) * 16);
        bCk[k] = (uint32_t)((((k << 1) + cbB) ^ sb) * 16);
    }

    const int lrow = tid >> 2;
    const int lch  = tid & 3;
    uint32_t stOff[2];
#pragma unroll
    for (int r = 0; r < 2; r++) {
        const int row = lrow + r * 64;
        stOff[r] = (uint32_t)(row * 64 + ((lch ^ ((row >> 1) & 3)) * 16));
    }
    const __nv_bfloat16* src[4][2];
#pragma unroll
    for (int r = 0; r < 2; r++) {
        src[0][r] = Ahi + (size_t)(bm + lrow + 64 * r) * K + lch * 8;
        src[1][r] = Alo + (size_t)(bm + lrow + 64 * r) * K + lch * 8;
        src[2][r] = Whi + (size_t)(bn + lrow + 64 * r) * K + lch * 8;
        src[3][r] = Wlo + (size_t)(bn + lrow + 64 * r) * K + lch * 8;
    }

    float acc[4][4][4];
#pragma unroll
    for (int i = 0; i < 4; i++)
#pragma unroll
        for (int j = 0; j < 4; j++)
#pragma unroll
            for (int e = 0; e < 4; e++) acc[i][j][e] = 0.0f;

    for (int kt = 0; kt < K; kt += 32) {
        __syncthreads();
#pragma unroll
        for (int t = 0; t < 4; t++)
#pragma unroll
            for (int r = 0; r < 2; r++)
                *reinterpret_cast<uint4*>(sT[t] + stOff[r]) =
                    *reinterpret_cast<const uint4*>(src[t][r] + kt);
        __syncthreads();

#pragma unroll
        for (int kx = 0; kx < 2; kx++) {
            uint32_t ah[16], wh[8], wl[8], al[16];
#pragma unroll
            for (int fm = 0; fm < 4; fm++)
                ldsm4(&ah[fm * 4], smem0 + 0 * 8192 + aRowB + fm * 1024 + aCk[kx]);
#pragma unroll
            for (int fp = 0; fp < 2; fp++)
                ldsm4(&wh[fp * 4], smem0 + 2 * 8192 + bRowB + fp * 1024 + bCk[kx]);
#pragma unroll
            for (int fm = 0; fm < 4; fm++)
#pragma unroll
                for (int fn = 0; fn < 4; fn++)
                    mma_bf16(acc[fm][fn], &ah[fm * 4], &wh[fn * 2]);
#pragma unroll
            for (int fp = 0; fp < 2; fp++)
                ldsm4(&wl[fp * 4], smem0 + 3 * 8192 + bRowB + fp * 1024 + bCk[kx]);
#pragma unroll
            for (int fm = 0; fm < 4; fm++)
#pragma unroll
                for (int fn = 0; fn < 4; fn++)
                    mma_bf16(acc[fm][fn], &ah[fm * 4], &wl[fn * 2]);
#pragma unroll
            for (int fm = 0; fm < 4; fm++)
                ldsm4(&al[fm * 4], smem0 + 1 * 8192 + aRowB + fm * 1024 + aCk[kx]);
#pragma unroll
            for (int fm = 0; fm < 4; fm++)
#pragma unroll
                for (int fn = 0; fn < 4; fn++)
                    mma_bf16(acc[fm][fn], &al[fm * 4], &wh[fn * 2]);
        }
    }

#pragma unroll
    for (int fm = 0; fm < 4; fm++) {
        const int m0 = bm + wm * 64 + fm * 16 + (lane >> 2);
#pragma unroll
        for (int fn = 0; fn < 4; fn++) {
            const int c0 = wn * 32 + fn * 8 + (lane & 3) * 2;
            float2 v0, v1;
            v0.x = acc[fm][fn][0] + bias_sm[c0];
            v0.y = acc[fm][fn][1] + bias_sm[c0 + 1];
            v1.x = acc[fm][fn][2] + bias_sm[c0];
            v1.y = acc[fm][fn][3] + bias_sm[c0 + 1];
            *(float2*)&C[(size_t)m0 * G4 + bn + c0] = v0;
            *(float2*)&C[(size_t)(m0 + 8) * G4 + bn + c0] = v1;
        }
    }
}

// =====================================================================
// init_state: zero bf16 h ping-pong planes + barrier state
// =====================================================================
__global__ void init_state()
{
    const int i = blockIdx.x * blockDim.x + threadIdx.x;   // 65536 threads
    unsigned* p = (unsigned*)g_hbf;                        // 131072 words
    for (int k = i; k < 131072; k += 65536) p[k] = 0u;
    if (i < 4) { g_cnt_leaf[0][i] = 0u; g_cnt_leaf[1][i] = 0u; }
    if (i < 2) { g_cnt_root[i] = 0u; g_gen[i] = 0u; }
}

// =====================================================================
// Per-direction tree barrier (scoped acq/rel atomics)
// =====================================================================
__device__ __forceinline__ void dir_barrier(int dir, int bx)
{
    __syncthreads();
    if (threadIdx.x == 0) {
        unsigned* gen_p = &g_gen[dir];
        const unsigned gen = ld_acq(gen_p);
        const int g = (bx & 63) >> 4;
        if (atom_add_acqrel(&g_cnt_leaf[dir][g], 1u) == 15u) {
            st_rlx(&g_cnt_leaf[dir][g], 0u);
            if (atom_add_acqrel(&g_cnt_root[dir], 1u) == 3u) {
                st_rlx(&g_cnt_root[dir], 0u);
                st_rel(gen_p, gen + 1u);
            } else {
                while (ld_acq(gen_p) == gen) { }
            }
        } else {
            while (ld_acq(gen_p) == gen) { }
        }
    }
    __syncthreads();
}

// =====================================================================
// Persistent recurrence via mma.sync, 3-term bf16 split.
// cp.async staging (deep MLP); optional fused a_hi/a_lo output for the
// next layer's GEMM (replaces the big split_bf16 pass over l0).
// =====================================================================
__global__ __launch_bounds__(256) void lstm_persist_mma(
    const float* __restrict__ xg_f, const float* __restrict__ xg_b,
    const float* __restrict__ whh_f, const float* __restrict__ whh_b,
    float* __restrict__ out,
    __nv_bfloat16* __restrict__ aH, __nv_bfloat16* __restrict__ aL)
{
    extern __shared__ char smc[];
    const uint32_t smem_u = s2u(smc);
    float* psm = (float*)(smc + OFF_PSM);

    const int tid  = threadIdx.x;
    const int bx   = blockIdx.x;
    const int dir  = bx >> 6;
    const int hb   = bx & 63;
    const int u0   = hb * 8;
    const int w    = tid >> 5;
    const int lane = tid & 31;
    const int wm   = w & 3;
    const int kh   = w >> 2;
    const int q    = lane >> 3;
    const int l7   = lane & 7;

    const float* xg  = dir ? xg_b : xg_f;
    const float* whh = dir ? whh_b : whh_f;

    // ---- one-time: split W slice (32 rows x 512) into smem bf16 hi/lo ----
    for (int ci = tid; ci < 32 * 64; ci += 256) {          // 16B chunks
        const int row = ci >> 6, c = ci & 63;
        const int grow = (row >> 3) * HID + u0 + (row & 7);
        const float4 f0 = __ldg((const float4*)&whh[(size_t)grow * HID + c * 8]);
        const float4 f1 = __ldg((const float4*)&whh[(size_t)grow * HID + c * 8 + 4]);
        unsigned h0, l0, h1, l1, h2, l2, h3, l3;
        split2(f0.x, f0.y, h0, l0); split2(f0.z, f0.w, h1, l1);
        split2(f1.x, f1.y, h2, l2); split2(f1.z, f1.w, h3, l3);
        const uint32_t dst = (uint32_t)(row * 1024 + ((c ^ (row & 7)) << 4));
        *(uint4*)(smc + OFF_WHI + dst) = make_uint4(h0, h1, h2, h3);
        *(uint4*)(smc + OFF_WLO + dst) = make_uint4(l0, l1, l2, l3);
    }
    __syncthreads();

    // ldmatrix lane geometry
    const int aRow = wm * 16 + (q & 1) * 8 + l7;           // A rows (batch)
    const int aSel = q >> 1;
    const int aXor = aRow & 7;
    const uint32_t aBase = (uint32_t)aRow * 1024;
    const int bRow = (q >> 1) * 8 + l7;                    // B rows (gates)
    const int bSel = q & 1;
    const int bXor = bRow & 7;
    const uint32_t bBase0 = (uint32_t)bRow * 1024;
    const uint32_t bBase1 = (uint32_t)(bRow + 16) * 1024;

    const int m0 = wm * 16 + (lane >> 2);                  // epilogue cells
    const int j2 = (lane & 3) * 2;
    const int uu2 = u0 + j2;

    float cst[2][2] = {{0.0f, 0.0f}, {0.0f, 0.0f}};        // c-state (kh==0)
    const int kb16 = kh * 16;

    for (int t = 0; t < T_LEN; t++) {
        const int t_eff = dir ? (T_LEN - 1 - t) : t;
        const int ping  = t & 1;
        const __nv_bfloat16* hpH = &g_hbf[dir][ping][0][0];
        const __nv_bfloat16* hpL = &g_hbf[dir][ping][1][0];
        __nv_bfloat16* hnH = &g_hbf[dir][ping ^ 1][0][0];
        __nv_bfloat16* hnL = &g_hbf[dir][ping ^ 1][1][0];

        // ---- stage h hi/lo planes via cp.async (deep MLP, no regs) ----
#pragma unroll
        for (int it = 0; it < 16; it++) {
            const int ci = tid + it * 256;                 // 0..4095
            const int row = ci >> 6, c = ci & 63;
            const uint32_t dst = (uint32_t)(row * 1024 + ((c ^ (row & 7)) << 4));
            cpa16(smem_u + OFF_HHI + dst, hpH + row * 512 + c * 8);
            cpa16(smem_u + OFF_HLO + dst, hpL + row * 512 + c * 8);
        }

        // prefetch xg gate rows while cp.async is in flight
        float2 xr[4][2];
        if (kh == 0) {
#pragma unroll
            for (int g = 0; g < 4; g++)
#pragma unroll
                for (int r = 0; r < 2; r++) {
                    const int b = m0 + r * 8;
                    xr[g][r] = __ldg((const float2*)
                        &xg[((size_t)t_eff * BATCH + b) * G4 + g * HID + uu2]);
                }
        }

        cpa_commit_wait();
        __syncthreads();

        // ---- mma over this warp's K-half: 16 k16 steps ----
        float acc[4][4];
#pragma unroll
        for (int fn = 0; fn < 4; fn++)
#pragma unroll
            for (int e = 0; e < 4; e++) acc[fn][e] = 0.0f;

#pragma unroll
        for (int kk = 0; kk < 16; kk++) {
            const int s = kb16 + kk;
            const uint32_t ca = (uint32_t)(((2 * s + aSel) ^ aXor) << 4);
            const uint32_t cb = (uint32_t)(((2 * s + bSel) ^ bXor) << 4);
            uint32_t ahi[4], alo[4], w0h[4], w1h[4], w0l[4], w1l[4];
            ldsm4(ahi, smem_u + OFF_HHI + aBase + ca);
            ldsm4(w0h, smem_u + OFF_WHI + bBase0 + cb);
            ldsm4(w1h, smem_u + OFF_WHI + bBase1 + cb);
            ldsm4(w0l, smem_u + OFF_WLO + bBase0 + cb);
            ldsm4(w1l, smem_u + OFF_WLO + bBase1 + cb);
            ldsm4(alo, smem_u + OFF_HLO + aBase + ca);
            mma_bf16(acc[0], ahi, w0h + 0);
            mma_bf16(acc[1], ahi, w0h + 2);
            mma_bf16(acc[2], ahi, w1h + 0);
            mma_bf16(acc[3], ahi, w1h + 2);
            mma_bf16(acc[0], ahi, w0l + 0);
            mma_bf16(acc[1], ahi, w0l + 2);
            mma_bf16(acc[2], ahi, w1l + 0);
            mma_bf16(acc[3], ahi, w1l + 2);
            mma_bf16(acc[0], alo, w0h + 0);
            mma_bf16(acc[1], alo, w0h + 2);
            mma_bf16(acc[2], alo, w1h + 0);
            mma_bf16(acc[3], alo, w1h + 2);
        }

        // ---- K-half reduction ----
        if (kh == 1) {
            float* pp = psm + (wm * 32 + lane) * 16;
#pragma unroll
            for (int fn = 0; fn < 4; fn++)
#pragma unroll
                for (int e = 0; e < 4; e++) pp[fn * 4 + e] = acc[fn][e];
        }
        __syncthreads();

        if (kh == 0) {
            const float* pp = psm + (wm * 32 + lane) * 16;
#pragma unroll
            for (int fn = 0; fn < 4; fn++)
#pragma unroll
                for (int e = 0; e < 4; e++) acc[fn][e] += pp[fn * 4 + e];

#pragma unroll
            for (int r = 0; r < 2; r++) {
                const int b = m0 + r * 8;
                float hv[2];
#pragma unroll
                for (int cc = 0; cc < 2; cc++) {
                    const int e = r * 2 + cc;
                    const float gi = acc[0][e] + (cc ? xr[0][r].y : xr[0][r].x);
                    const float gf = acc[1][e] + (cc ? xr[1][r].y : xr[1][r].x);
                    const float gg = acc[2][e] + (cc ? xr[2][r].y : xr[2][r].x);
                    const float go = acc[3][e] + (cc ? xr[3][r].y : xr[3][r].x);
                    cst[r][cc] = sigf(gf) * cst[r][cc] + sigf(gi) * tanhf(gg);
                    hv[cc] = sigf(go) * tanhf(cst[r][cc]);
                }
                unsigned ph, pl;
                split2(hv[0], hv[1], ph, pl);
                __stcg((unsigned*)(hnH + b * 512 + uu2), ph);
                __stcg((unsigned*)(hnL + b * 512 + uu2), pl);
                if (aH) {
                    // fused next-layer GEMM operand: A[t*64+b, dir*512+u]
                    const size_t arow = ((size_t)t_eff * BATCH + b) * 1024
                                        + dir * HID + uu2;
                    __stcg((unsigned*)(aH + arow), ph);
                    __stcg((unsigned*)(aL + arow), pl);
                } else {
                    *(float2*)&out[((size_t)t_eff * BATCH + b) * (2 * HID)
                                   + dir * HID + uu2] = make_float2(hv[0], hv[1]);
                }
            }
        }

        dir_barrier(dir, bx);
    }
}

// =====================================================================
// host
// =====================================================================
extern "C" void kernel_launch(void* const* d_in, const int* in_sizes, int n_in,
                              void* d_out, int out_size)
{
    const float* x       = (const float*)d_in[0];
    const float* w_ih0_f = (const float*)d_in[1];
    const float* w_hh0_f = (const float*)d_in[2];
    const float* b_ih0_f = (const float*)d_in[3];
    const float* b_hh0_f = (const float*)d_in[4];
    const float* w_ih0_b = (const float*)d_in[5];
    const float* w_hh0_b = (const float*)d_in[6];
    const float* b_ih0_b = (const float*)d_in[7];
    const float* b_hh0_b = (const float*)d_in[8];
    const float* w_ih1_f = (const float*)d_in[9];
    const float* w_hh1_f = (const float*)d_in[10];
    const float* b_ih1_f = (const float*)d_in[11];
    const float* b_hh1_f = (const float*)d_in[12];
    const float* w_ih1_b = (const float*)d_in[13];
    const float* w_hh1_b = (const float*)d_in[14];
    const float* b_ih1_b = (const float*)d_in[15];
    const float* b_hh1_b = (const float*)d_in[16];
    float* out = (float*)d_out;

    float *xg_f, *xg_b, *l0;
    __nv_bfloat16 *a_hi, *a_lo, *whi_f, *wlo_f, *whi_b, *wlo_b;
    cudaGetSymbolAddress((void**)&xg_f,  g_xg_f);
    cudaGetSymbolAddress((void**)&xg_b,  g_xg_b);
    cudaGetSymbolAddress((void**)&l0,    g_l0);
    cudaGetSymbolAddress((void**)&a_hi,  g_a_hi);
    cudaGetSymbolAddress((void**)&a_lo,  g_a_lo);
    cudaGetSymbolAddress((void**)&whi_f, g_whi_f);
    cudaGetSymbolAddress((void**)&wlo_f, g_wlo_f);
    cudaGetSymbolAddress((void**)&whi_b, g_whi_b);
    cudaGetSymbolAddress((void**)&wlo_b, g_wlo_b);

    cudaFuncSetAttribute(lstm_persist_mma,
                         cudaFuncAttributeMaxDynamicSharedMemorySize, RSMEM_BYTES);

    const dim3 gemm_grid(G4 / 128, MROWS / 128);   // (16, 256)

    // ---- layer 0: split + mma GEMMs (K=512) ----
    split_bf16<<<512, 256>>>(x,       a_hi,  a_lo,  (size_t)MROWS * 512);
    split_bf16<<<256, 256>>>(w_ih0_f, whi_f, wlo_f, (size_t)G4 * 512);
    split_bf16<<<256, 256>>>(w_ih0_b, whi_b, wlo_b, (size_t)G4 * 512);
    gemm_mma<<<gemm_grid, 256>>>(a_hi, a_lo, whi_f, wlo_f, b_ih0_f, b_hh0_f, xg_f, 512);
    gemm_mma<<<gemm_grid, 256>>>(a_hi, a_lo, whi_b, wlo_b, b_ih0_b, b_hh0_b, xg_b, 512);
    init_state<<<256, 256>>>();
    // layer-0 recurrence writes a_hi/a_lo (next layer's A operand) directly
    lstm_persist_mma<<<NBLK, 256, RSMEM_BYTES>>>(xg_f, xg_b, w_hh0_f, w_hh0_b,
                                                 l0, a_hi, a_lo);

    // ---- layer 1: weight splits + mma GEMMs (K=1024) ----
    split_bf16<<<256, 256>>>(w_ih1_f, whi_f, wlo_f, (size_t)G4 * 1024);
    split_bf16<<<256, 256>>>(w_ih1_b, whi_b, wlo_b, (size_t)G4 * 1024);
    gemm_mma<<<gemm_grid, 256>>>(a_hi, a_lo, whi_f, wlo_f, b_ih1_f, b_hh1_f, xg_f, 1024);
    gemm_mma<<<gemm_grid, 256>>>(a_hi, a_lo, whi_b, wlo_b, b_ih1_b, b_hh1_b, xg_b, 1024);
    init_state<<<256, 256>>>();
    lstm_persist_mma<<<NBLK, 256, RSMEM_BYTES>>>(xg_f, xg_b, w_hh1_f, w_hh1_b,
                                                 out, nullptr, nullptr);
}

// round 12
// speedup vs baseline: 2.7114x; 1.1127x over previous
#include <cuda_runtime.h>
#include <cuda_bf16.h>
#include <cuda_fp16.h>
#include <cstdint>
#include <math.h>

// LSTM_38646115729591 — 2-layer bidirectional LSTM.
// T=512, B=64, D=512, H=512. Output [T,B,2H] fp32.
// Input GEMMs: mma.sync bf16, 2-term hi/lo split.
// Recurrence: persistent mma.sync fp16 (h and W_hh fp16), 16 warps/block.

#define T_LEN 512
#define BATCH 64
#define HID   512
#define G4    2048
#define MROWS (T_LEN * BATCH)   // 32768
#define NBLK  128

// recurrence smem layout (bytes)
#define OFF_W   0                 // 32 rows x 512 fp16 = 32768
#define OFF_H   32768             // 64 rows x 512 fp16 = 65536
#define OFF_PSM 98304             // 3 * 8192 reduction scratch
#define RSMEM_BYTES (98304 + 24576)   // 122880

typedef unsigned long long ull;

// ---- static device scratch ----
__device__ float g_xg_f[(size_t)MROWS * G4];
__device__ float g_xg_b[(size_t)MROWS * G4];
__device__ float g_l0[(size_t)MROWS * 2 * HID];
__device__ __half g_hfp[2][2][BATCH * HID];     // [dir][ping] fp16 h
__device__ unsigned g_cnt_leaf[2][4];
__device__ unsigned g_cnt_root[2];
__device__ unsigned g_gen[2];

__device__ __nv_bfloat16 g_a_hi[(size_t)MROWS * 1024];
__device__ __nv_bfloat16 g_a_lo[(size_t)MROWS * 1024];
__device__ __nv_bfloat16 g_whi_f[(size_t)G4 * 1024];
__device__ __nv_bfloat16 g_wlo_f[(size_t)G4 * 1024];
__device__ __nv_bfloat16 g_whi_b[(size_t)G4 * 1024];
__device__ __nv_bfloat16 g_wlo_b[(size_t)G4 * 1024];

__device__ __forceinline__ float sigf(float x) { return 1.0f / (1.0f + __expf(-x)); }

// ---- scoped sync primitives ----
__device__ __forceinline__ unsigned atom_add_acqrel(unsigned* p, unsigned v) {
    unsigned old;
    asm volatile("atom.add.acq_rel.gpu.u32 %0, [%1], %2;"
                 : "=r"(old) : "l"(p), "r"(v) : "memory");
    return old;
}
__device__ __forceinline__ unsigned ld_acq(const unsigned* p) {
    unsigned v;
    asm volatile("ld.acquire.gpu.u32 %0, [%1];" : "=r"(v) : "l"(p) : "memory");
    return v;
}
__device__ __forceinline__ void st_rel(unsigned* p, unsigned v) {
    asm volatile("st.release.gpu.u32 [%0], %1;" :: "l"(p), "r"(v) : "memory");
}
__device__ __forceinline__ void st_rlx(unsigned* p, unsigned v) {
    asm volatile("st.relaxed.gpu.u32 [%0], %1;" :: "l"(p), "r"(v) : "memory");
}

// ---- mma.sync / cp.async helpers (sm_80 PTX — valid on compute_103) ----
__device__ __forceinline__ uint32_t s2u(const void* p) {
    return (uint32_t)__cvta_generic_to_shared(p);
}
__device__ __forceinline__ void ldsm4(uint32_t* r, uint32_t addr) {
    asm volatile(
        "ldmatrix.sync.aligned.m8n8.x4.shared.b16 {%0,%1,%2,%3}, [%4];"
        : "=r"(r[0]), "=r"(r[1]), "=r"(r[2]), "=r"(r[3]) : "r"(addr));
}
__device__ __forceinline__ void mma_bf16(float* d, const uint32_t* a,
                                         const uint32_t* b) {
    asm volatile(
        "mma.sync.aligned.m16n8k16.row.col.f32.bf16.bf16.f32 "
        "{%0,%1,%2,%3}, {%4,%5,%6,%7}, {%8,%9}, {%0,%1,%2,%3};"
        : "+f"(d[0]), "+f"(d[1]), "+f"(d[2]), "+f"(d[3])
        : "r"(a[0]), "r"(a[1]), "r"(a[2]), "r"(a[3]), "r"(b[0]), "r"(b[1]));
}
__device__ __forceinline__ void mma_f16(float* d, const uint32_t* a,
                                        const uint32_t* b) {
    asm volatile(
        "mma.sync.aligned.m16n8k16.row.col.f32.f16.f16.f32 "
        "{%0,%1,%2,%3}, {%4,%5,%6,%7}, {%8,%9}, {%0,%1,%2,%3};"
        : "+f"(d[0]), "+f"(d[1]), "+f"(d[2]), "+f"(d[3])
        : "r"(a[0]), "r"(a[1]), "r"(a[2]), "r"(a[3]), "r"(b[0]), "r"(b[1]));
}
__device__ __forceinline__ void cpa16(uint32_t smem_dst, const void* gsrc) {
    asm volatile("cp.async.cg.shared.global [%0], [%1], 16;"
                 :: "r"(smem_dst), "l"(__cvta_generic_to_global(gsrc))
                 : "memory");
}
__device__ __forceinline__ void cpa_commit_wait() {
    asm volatile("cp.async.commit_group;" ::: "memory");
    asm volatile("cp.async.wait_group 0;" ::: "memory");
}
// split two floats into packed bf16 hi-pair and lo-pair (residual)
__device__ __forceinline__ void split2(float a, float b,
                                       unsigned& h, unsigned& l) {
    const __nv_bfloat16 ha = __float2bfloat16_rn(a);
    const __nv_bfloat16 hb = __float2bfloat16_rn(b);
    const float ra = a - __bfloat162float(ha);
    const float rb = b - __bfloat162float(hb);
    h = (unsigned)__bfloat16_as_ushort(ha)
      | ((unsigned)__bfloat16_as_ushort(hb) << 16);
    l = (unsigned)__bfloat16_as_ushort(__float2bfloat16_rn(ra))
      | ((unsigned)__bfloat16_as_ushort(__float2bfloat16_rn(rb)) << 16);
}
__device__ __forceinline__ unsigned packh2(float a, float b) {
    const __half2 h2 = __floats2half2_rn(a, b);
    return *(const unsigned*)&h2;
}

// =====================================================================
// split_bf16: v -> hi = bf16(v), lo = bf16(v - hi)
// =====================================================================
__global__ void split_bf16(const float* __restrict__ src,
                           __nv_bfloat16* __restrict__ hi,
                           __nv_bfloat16* __restrict__ lo,
                           size_t n)
{
    size_t i = (size_t)blockIdx.x * blockDim.x + threadIdx.x;
    const size_t stride = (size_t)gridDim.x * blockDim.x;
    for (; i < n; i += stride) {
        const float v = src[i];
        const __nv_bfloat16 h = __float2bfloat16_rn(v);
        const float r = v - __bfloat162float(h);
        hi[i] = h;
        lo[i] = __float2bfloat16_rn(r);
    }
}

// =====================================================================
// gemm_mma (round-9/10/11 passing version, unchanged)
// =====================================================================
__global__ __launch_bounds__(256, 2)
void gemm_mma(const __nv_bfloat16* __restrict__ Ahi,
              const __nv_bfloat16* __restrict__ Alo,
              const __nv_bfloat16* __restrict__ Whi,
              const __nv_bfloat16* __restrict__ Wlo,
              const float* __restrict__ b1, const float* __restrict__ b2,
              float* __restrict__ C, int K)
{
    __shared__ alignas(128) char sT[4][8192];
    __shared__ float bias_sm[128];

    const int tid  = threadIdx.x;
    const int wid  = tid >> 5;
    const int lane = tid & 31;
    const int bm   = blockIdx.y * 128;
    const int bn   = blockIdx.x * 128;
    const int wm   = wid & 1;
    const int wn   = wid >> 1;

    if (tid < 128) bias_sm[tid] = b1[bn + tid] + b2[bn + tid];

    const int q   = lane >> 3;
    const int rA  = (q & 1) * 8 + (lane & 7);
    const int caA = q >> 1;
    const int sa  = (rA >> 1) & 3;
    const int rB  = (q >> 1) * 8 + (lane & 7);
    const int cbB = q & 1;
    const int sb  = (rB >> 1) & 3;

    const uint32_t smem0 = s2u(sT);
    const uint32_t aRowB = (uint32_t)(wm * 64 + rA) * 64;
    const uint32_t bRowB = (uint32_t)(wn * 32 + rB) * 64;
    uint32_t aCk[2], bCk[2];
#pragma unroll
    for (int k = 0; k < 2; k++) {
        aCk[k] = (uint32_t)((((k << 1) + caA) ^ sa) * 16);
        bCk[k] = (uint32_t)((((k << 1) + cbB) ^ sb) * 16);
    }

    const int lrow = tid >> 2;
    const int lch  = tid & 3;
    uint32_t stOff[2];
#pragma unroll
    for (int r = 0; r < 2; r++) {
        const int row = lrow + r * 64;
        stOff[r] = (uint32_t)(row * 64 + ((lch ^ ((row >> 1) & 3)) * 16));
    }
    const __nv_bfloat16* src[4][2];
#pragma unroll
    for (int r = 0; r < 2; r++) {
        src[0][r] = Ahi + (size_t)(bm + lrow + 64 * r) * K + lch * 8;
        src[1][r] = Alo + (size_t)(bm + lrow + 64 * r) * K + lch * 8;
        src[2][r] = Whi + (size_t)(bn + lrow + 64 * r) * K + lch * 8;
        src[3][r] = Wlo + (size_t)(bn + lrow + 64 * r) * K + lch * 8;
    }

    float acc[4][4][4];
#pragma unroll
    for (int i = 0; i < 4; i++)
#pragma unroll
        for (int j = 0; j < 4; j++)
#pragma unroll
            for (int e = 0; e < 4; e++) acc[i][j][e] = 0.0f;

    for (int kt = 0; kt < K; kt += 32) {
        __syncthreads();
#pragma unroll
        for (int t = 0; t < 4; t++)
#pragma unroll
            for (int r = 0; r < 2; r++)
                *reinterpret_cast<uint4*>(sT[t] + stOff[r]) =
                    *reinterpret_cast<const uint4*>(src[t][r] + kt);
        __syncthreads();

#pragma unroll
        for (int kx = 0; kx < 2; kx++) {
            uint32_t ah[16], wh[8], wl[8], al[16];
#pragma unroll
            for (int fm = 0; fm < 4; fm++)
                ldsm4(&ah[fm * 4], smem0 + 0 * 8192 + aRowB + fm * 1024 + aCk[kx]);
#pragma unroll
            for (int fp = 0; fp < 2; fp++)
                ldsm4(&wh[fp * 4], smem0 + 2 * 8192 + bRowB + fp * 1024 + bCk[kx]);
#pragma unroll
            for (int fm = 0; fm < 4; fm++)
#pragma unroll
                for (int fn = 0; fn < 4; fn++)
                    mma_bf16(acc[fm][fn], &ah[fm * 4], &wh[fn * 2]);
#pragma unroll
            for (int fp = 0; fp < 2; fp++)
                ldsm4(&wl[fp * 4], smem0 + 3 * 8192 + bRowB + fp * 1024 + bCk[kx]);
#pragma unroll
            for (int fm = 0; fm < 4; fm++)
#pragma unroll
                for (int fn = 0; fn < 4; fn++)
                    mma_bf16(acc[fm][fn], &ah[fm * 4], &wl[fn * 2]);
#pragma unroll
            for (int fm = 0; fm < 4; fm++)
                ldsm4(&al[fm * 4], smem0 + 1 * 8192 + aRowB + fm * 1024 + aCk[kx]);
#pragma unroll
            for (int fm = 0; fm < 4; fm++)
#pragma unroll
                for (int fn = 0; fn < 4; fn++)
                    mma_bf16(acc[fm][fn], &al[fm * 4], &wh[fn * 2]);
        }
    }

#pragma unroll
    for (int fm = 0; fm < 4; fm++) {
        const int m0 = bm + wm * 64 + fm * 16 + (lane >> 2);
#pragma unroll
        for (int fn = 0; fn < 4; fn++) {
            const int c0 = wn * 32 + fn * 8 + (lane & 3) * 2;
            float2 v0, v1;
            v0.x = acc[fm][fn][0] + bias_sm[c0];
            v0.y = acc[fm][fn][1] + bias_sm[c0 + 1];
            v1.x = acc[fm][fn][2] + bias_sm[c0];
            v1.y = acc[fm][fn][3] + bias_sm[c0 + 1];
            *(float2*)&C[(size_t)m0 * G4 + bn + c0] = v0;
            *(float2*)&C[(size_t)(m0 + 8) * G4 + bn + c0] = v1;
        }
    }
}

// =====================================================================
// init_state: zero fp16 h ping-pong planes + barrier state
// =====================================================================
__global__ void init_state()
{
    const int i = blockIdx.x * blockDim.x + threadIdx.x;   // 65536 threads
    unsigned* p = (unsigned*)g_hfp;                        // 65536 words
    p[i] = 0u;
    if (i < 4) { g_cnt_leaf[0][i] = 0u; g_cnt_leaf[1][i] = 0u; }
    if (i < 2) { g_cnt_root[i] = 0u; g_gen[i] = 0u; }
}

// =====================================================================
// Per-direction tree barrier (scoped acq/rel atomics)
// =====================================================================
__device__ __forceinline__ void dir_barrier(int dir, int bx)
{
    __syncthreads();
    if (threadIdx.x == 0) {
        unsigned* gen_p = &g_gen[dir];
        const unsigned gen = ld_acq(gen_p);
        const int g = (bx & 63) >> 4;
        if (atom_add_acqrel(&g_cnt_leaf[dir][g], 1u) == 15u) {
            st_rlx(&g_cnt_leaf[dir][g], 0u);
            if (atom_add_acqrel(&g_cnt_root[dir], 1u) == 3u) {
                st_rlx(&g_cnt_root[dir], 0u);
                st_rel(gen_p, gen + 1u);
            } else {
                while (ld_acq(gen_p) == gen) { }
            }
        } else {
            while (ld_acq(gen_p) == gen) { }
        }
    }
    __syncthreads();
}

// =====================================================================
// Persistent recurrence via fp16 mma.sync.
// 128 blocks x 512 thr: dir = bx/64, hb = bx%64 -> 32 W rows (n = g*8+j).
// Warps: wm = w&3 (16 batch rows), kq = w>>2 (K-quarter, 8 k16 steps).
// Per k16: 3 ldsm4 + 4 mma. Lane owns all 4 gates of its (batch, unit).
// h ping-pong in global fp16; W_hh fp16 resident in smem.
// =====================================================================
__global__ __launch_bounds__(512) void lstm_persist_mma(
    const float* __restrict__ xg_f, const float* __restrict__ xg_b,
    const float* __restrict__ whh_f, const float* __restrict__ whh_b,
    float* __restrict__ out,
    __nv_bfloat16* __restrict__ aH, __nv_bfloat16* __restrict__ aL)
{
    extern __shared__ char smc[];
    const uint32_t smem_u = s2u(smc);
    float* psm = (float*)(smc + OFF_PSM);

    const int tid  = threadIdx.x;
    const int bx   = blockIdx.x;
    const int dir  = bx >> 6;
    const int hb   = bx & 63;
    const int u0   = hb * 8;
    const int w    = tid >> 5;
    const int lane = tid & 31;
    const int wm   = w & 3;
    const int kq   = w >> 2;                               // 0..3
    const int q    = lane >> 3;
    const int l7   = lane & 7;

    const float* xg  = dir ? xg_b : xg_f;
    const float* whh = dir ? whh_b : whh_f;

    // ---- one-time: W slice (32 rows x 512) -> smem fp16, swizzled ----
    for (int ci = tid; ci < 32 * 64; ci += 512) {          // 16B chunks
        const int row = ci >> 6, c = ci & 63;
        const int grow = (row >> 3) * HID + u0 + (row & 7);
        const float4 f0 = __ldg((const float4*)&whh[(size_t)grow * HID + c * 8]);
        const float4 f1 = __ldg((const float4*)&whh[(size_t)grow * HID + c * 8 + 4]);
        const uint4 v = make_uint4(packh2(f0.x, f0.y), packh2(f0.z, f0.w),
                                   packh2(f1.x, f1.y), packh2(f1.z, f1.w));
        const uint32_t dst = (uint32_t)(row * 1024 + ((c ^ (row & 7)) << 4));
        *(uint4*)(smc + OFF_W + dst) = v;
    }
    __syncthreads();

    // ldmatrix lane geometry (identical frag pattern to round 9-11)
    const int aRow = wm * 16 + (q & 1) * 8 + l7;           // A rows (batch)
    const int aSel = q >> 1;
    const int aXor = aRow & 7;
    const uint32_t aBase = (uint32_t)aRow * 1024;
    const int bRow = (q >> 1) * 8 + l7;                    // B rows (gates)
    const int bSel = q & 1;
    const int bXor = bRow & 7;
    const uint32_t bBase0 = (uint32_t)bRow * 1024;
    const uint32_t bBase1 = (uint32_t)(bRow + 16) * 1024;

    const int m0 = wm * 16 + (lane >> 2);                  // epilogue cells
    const int j2 = (lane & 3) * 2;
    const int uu2 = u0 + j2;

    float cst[2][2] = {{0.0f, 0.0f}, {0.0f, 0.0f}};        // c-state (kq==0)
    const int kb8 = kq * 8;

    for (int t = 0; t < T_LEN; t++) {
        const int t_eff = dir ? (T_LEN - 1 - t) : t;
        const int ping  = t & 1;
        const __half* hp = &g_hfp[dir][ping][0];
        __half*       hn = &g_hfp[dir][ping ^ 1][0];

        // ---- stage h plane (64 x 512 fp16) via cp.async ----
#pragma unroll
        for (int it = 0; it < 8; it++) {
            const int ci = tid + it * 512;                 // 0..4095
            const int row = ci >> 6, c = ci & 63;
            const uint32_t dst = (uint32_t)(row * 1024 + ((c ^ (row & 7)) << 4));
            cpa16(smem_u + OFF_H + dst, hp + row * 512 + c * 8);
        }

        // prefetch xg gate rows while cp.async is in flight
        float2 xr[4][2];
        if (kq == 0) {
#pragma unroll
            for (int g = 0; g < 4; g++)
#pragma unroll
                for (int r = 0; r < 2; r++) {
                    const int b = m0 + r * 8;
                    xr[g][r] = __ldg((const float2*)
                        &xg[((size_t)t_eff * BATCH + b) * G4 + g * HID + uu2]);
                }
        }

        cpa_commit_wait();
        __syncthreads();

        // ---- mma over this warp's K-quarter: 8 k16 steps ----
        float acc[4][4];
#pragma unroll
        for (int fn = 0; fn < 4; fn++)
#pragma unroll
            for (int e = 0; e < 4; e++) acc[fn][e] = 0.0f;

#pragma unroll
        for (int kk = 0; kk < 8; kk++) {
            const int s = kb8 + kk;
            const uint32_t ca = (uint32_t)(((2 * s + aSel) ^ aXor) << 4);
            const uint32_t cb = (uint32_t)(((2 * s + bSel) ^ bXor) << 4);
            uint32_t a[4], w0[4], w1[4];
            ldsm4(a,  smem_u + OFF_H + aBase + ca);
            ldsm4(w0, smem_u + OFF_W + bBase0 + cb);
            ldsm4(w1, smem_u + OFF_W + bBase1 + cb);
            mma_f16(acc[0], a, w0 + 0);
            mma_f16(acc[1], a, w0 + 2);
            mma_f16(acc[2], a, w1 + 0);
            mma_f16(acc[3], a, w1 + 2);
        }

        // ---- K-quarter reduction (kq 1..3 -> psm; kq 0 finalizes) ----
        if (kq != 0) {
            float* pp = psm + ((kq - 1) * 128 + wm * 32 + lane) * 16;
#pragma unroll
            for (int fn = 0; fn < 4; fn++)
#pragma unroll
                for (int e = 0; e < 4; e++) pp[fn * 4 + e] = acc[fn][e];
        }
        __syncthreads();

        if (kq == 0) {
#pragma unroll
            for (int kqq = 0; kqq < 3; kqq++) {
                const float* pp = psm + (kqq * 128 + wm * 32 + lane) * 16;
#pragma unroll
                for (int fn = 0; fn < 4; fn++)
#pragma unroll
                    for (int e = 0; e < 4; e++) acc[fn][e] += pp[fn * 4 + e];
            }

#pragma unroll
            for (int r = 0; r < 2; r++) {
                const int b = m0 + r * 8;
                float hv[2];
#pragma unroll
                for (int cc = 0; cc < 2; cc++) {
                    const int e = r * 2 + cc;
                    const float gi = acc[0][e] + (cc ? xr[0][r].y : xr[0][r].x);
                    const float gf = acc[1][e] + (cc ? xr[1][r].y : xr[1][r].x);
                    const float gg = acc[2][e] + (cc ? xr[2][r].y : xr[2][r].x);
                    const float go = acc[3][e] + (cc ? xr[3][r].y : xr[3][r].x);
                    cst[r][cc] = sigf(gf) * cst[r][cc] + sigf(gi) * tanhf(gg);
                    hv[cc] = sigf(go) * tanhf(cst[r][cc]);
                }
                __stcg((unsigned*)(hn + b * 512 + uu2), packh2(hv[0], hv[1]));
                if (aH) {
                    // fused next-layer GEMM operand: A[t*64+b, dir*512+u]
                    unsigned ph, pl;
                    split2(hv[0], hv[1], ph, pl);
                    const size_t arow = ((size_t)t_eff * BATCH + b) * 1024
                                        + dir * HID + uu2;
                    __stcg((unsigned*)(aH + arow), ph);
                    __stcg((unsigned*)(aL + arow), pl);
                } else {
                    *(float2*)&out[((size_t)t_eff * BATCH + b) * (2 * HID)
                                   + dir * HID + uu2] = make_float2(hv[0], hv[1]);
                }
            }
        }

        dir_barrier(dir, bx);
    }
}

// =====================================================================
// host
// =====================================================================
extern "C" void kernel_launch(void* const* d_in, const int* in_sizes, int n_in,
                              void* d_out, int out_size)
{
    const float* x       = (const float*)d_in[0];
    const float* w_ih0_f = (const float*)d_in[1];
    const float* w_hh0_f = (const float*)d_in[2];
    const float* b_ih0_f = (const float*)d_in[3];
    const float* b_hh0_f = (const float*)d_in[4];
    const float* w_ih0_b = (const float*)d_in[5];
    const float* w_hh0_b = (const float*)d_in[6];
    const float* b_ih0_b = (const float*)d_in[7];
    const float* b_hh0_b = (const float*)d_in[8];
    const float* w_ih1_f = (const float*)d_in[9];
    const float* w_hh1_f = (const float*)d_in[10];
    const float* b_ih1_f = (const float*)d_in[11];
    const float* b_hh1_f = (const float*)d_in[12];
    const float* w_ih1_b = (const float*)d_in[13];
    const float* w_hh1_b = (const float*)d_in[14];
    const float* b_ih1_b = (const float*)d_in[15];
    const float* b_hh1_b = (const float*)d_in[16];
    float* out = (float*)d_out;

    float *xg_f, *xg_b, *l0;
    __nv_bfloat16 *a_hi, *a_lo, *whi_f, *wlo_f, *whi_b, *wlo_b;
    cudaGetSymbolAddress((void**)&xg_f,  g_xg_f);
    cudaGetSymbolAddress((void**)&xg_b,  g_xg_b);
    cudaGetSymbolAddress((void**)&l0,    g_l0);
    cudaGetSymbolAddress((void**)&a_hi,  g_a_hi);
    cudaGetSymbolAddress((void**)&a_lo,  g_a_lo);
    cudaGetSymbolAddress((void**)&whi_f, g_whi_f);
    cudaGetSymbolAddress((void**)&wlo_f, g_wlo_f);
    cudaGetSymbolAddress((void**)&whi_b, g_whi_b);
    cudaGetSymbolAddress((void**)&wlo_b, g_wlo_b);

    cudaFuncSetAttribute(lstm_persist_mma,
                         cudaFuncAttributeMaxDynamicSharedMemorySize, RSMEM_BYTES);

    const dim3 gemm_grid(G4 / 128, MROWS / 128);   // (16, 256)

    // ---- layer 0: split + mma GEMMs (K=512) ----
    split_bf16<<<512, 256>>>(x,       a_hi,  a_lo,  (size_t)MROWS * 512);
    split_bf16<<<256, 256>>>(w_ih0_f, whi_f, wlo_f, (size_t)G4 * 512);
    split_bf16<<<256, 256>>>(w_ih0_b, whi_b, wlo_b, (size_t)G4 * 512);
    gemm_mma<<<gemm_grid, 256>>>(a_hi, a_lo, whi_f, wlo_f, b_ih0_f, b_hh0_f, xg_f, 512);
    gemm_mma<<<gemm_grid, 256>>>(a_hi, a_lo, whi_b, wlo_b, b_ih0_b, b_hh0_b, xg_b, 512);
    init_state<<<256, 256>>>();
    // layer-0 recurrence writes a_hi/a_lo (next layer's A operand) directly
    lstm_persist_mma<<<NBLK, 512, RSMEM_BYTES>>>(xg_f, xg_b, w_hh0_f, w_hh0_b,
                                                 l0, a_hi, a_lo);

    // ---- layer 1: weight splits + mma GEMMs (K=1024) ----
    split_bf16<<<256, 256>>>(w_ih1_f, whi_f, wlo_f, (size_t)G4 * 1024);
    split_bf16<<<256, 256>>>(w_ih1_b, whi_b, wlo_b, (size_t)G4 * 1024);
    gemm_mma<<<gemm_grid, 256>>>(a_hi, a_lo, whi_f, wlo_f, b_ih1_f, b_hh1_f, xg_f, 1024);
    gemm_mma<<<gemm_grid, 256>>>(a_hi, a_lo, whi_b, wlo_b, b_ih1_b, b_hh1_b, xg_b, 1024);
    init_state<<<256, 256>>>();
    lstm_persist_mma<<<NBLK, 512, RSMEM_BYTES>>>(xg_f, xg_b, w_hh1_f, w_hh1_b,
                                                 out, nullptr, nullptr);
}